// round 1
// baseline (speedup 1.0000x reference)
#include <cuda_runtime.h>
#include <math.h>

// Problem constants
#define BATCH 16
#define SEQ   2048
#define DIM   512
#define MROWS (BATCH * SEQ)   // 32768
#define SCALE 0.125f

// SGEMM tile config
#define BM 128
#define BN 128
#define BK 8
#define TM 8
#define TN 8
#define NTHREADS 256  // (BM/TM)*(BN/TN)

// ---------------------------------------------------------------------------
// Scratch (device globals — no allocation allowed in kernel_launch)
// ---------------------------------------------------------------------------
__device__ float g_q[(long)MROWS * DIM];
__device__ float g_k[(long)MROWS * DIM];
__device__ float g_v[(long)MROWS * DIM];
__device__ float g_sim[(long)BATCH * SEQ * SEQ];

// ---------------------------------------------------------------------------
// NN GEMM: C[M,N] = A[M,K] (row-major) * B[K,N] (row-major) + bias (optional)
// All of M%BM==0, N%BN==0, K%BK==0 guaranteed by launch sites.
// Batched via blockIdx.z with element strides.
// ---------------------------------------------------------------------------
__global__ __launch_bounds__(NTHREADS)
void sgemm_nn(const float* __restrict__ A, const float* __restrict__ B,
              const float* __restrict__ bias, float* __restrict__ C,
              int M, int N, int K,
              long strideA, long strideB, long strideC)
{
    A += (long)blockIdx.z * strideA;
    B += (long)blockIdx.z * strideB;
    C += (long)blockIdx.z * strideC;

    __shared__ float As[BK][BM];
    __shared__ float Bs[BK][BN];

    const int tid  = threadIdx.x;
    const int row0 = blockIdx.y * BM;
    const int col0 = blockIdx.x * BN;

    // A tile loads: 128 rows x 8 cols -> one float4 per thread
    const int aRow  = tid >> 1;          // 0..127
    const int aCol4 = (tid & 1) * 4;     // 0 or 4
    // B tile loads: 8 rows x 128 cols -> one float4 per thread
    const int bRow  = tid >> 5;          // 0..7
    const int bCol4 = (tid & 31) * 4;    // 0..124

    const int tx = tid & 15;             // output col group
    const int ty = tid >> 4;             // output row group

    float acc[TM][TN] = {};
    float ar[TM], br[TN];

    for (int k0 = 0; k0 < K; k0 += BK) {
        float4 av = *(const float4*)(A + (long)(row0 + aRow) * K + k0 + aCol4);
        As[aCol4 + 0][aRow] = av.x;
        As[aCol4 + 1][aRow] = av.y;
        As[aCol4 + 2][aRow] = av.z;
        As[aCol4 + 3][aRow] = av.w;
        *(float4*)&Bs[bRow][bCol4] =
            *(const float4*)(B + (long)(k0 + bRow) * N + col0 + bCol4);
        __syncthreads();

        #pragma unroll
        for (int k = 0; k < BK; k++) {
            #pragma unroll
            for (int i = 0; i < TM; i++) ar[i] = As[k][ty * TM + i];
            #pragma unroll
            for (int j = 0; j < TN; j++) br[j] = Bs[k][tx * TN + j];
            #pragma unroll
            for (int i = 0; i < TM; i++)
                #pragma unroll
                for (int j = 0; j < TN; j++)
                    acc[i][j] = fmaf(ar[i], br[j], acc[i][j]);
        }
        __syncthreads();
    }

    #pragma unroll
    for (int i = 0; i < TM; i++) {
        const int r = row0 + ty * TM + i;
        #pragma unroll
        for (int j = 0; j < TN; j += 4) {
            const int c = col0 + tx * TN + j;
            float4 v;
            v.x = acc[i][j + 0];
            v.y = acc[i][j + 1];
            v.z = acc[i][j + 2];
            v.w = acc[i][j + 3];
            if (bias) {
                v.x += bias[c + 0];
                v.y += bias[c + 1];
                v.z += bias[c + 2];
                v.w += bias[c + 3];
            }
            *(float4*)(C + (long)r * N + c) = v;
        }
    }
}

// ---------------------------------------------------------------------------
// NT GEMM: C[M,N] = alpha * A[M,K] * B[N,K]^T  (both row-major)
// Used for sim = Q @ K^T * scale, batched over blockIdx.z.
// ---------------------------------------------------------------------------
__global__ __launch_bounds__(NTHREADS)
void sgemm_nt(const float* __restrict__ A, const float* __restrict__ Bm,
              float* __restrict__ C,
              int M, int N, int K, float alpha,
              long strideA, long strideB, long strideC)
{
    A  += (long)blockIdx.z * strideA;
    Bm += (long)blockIdx.z * strideB;
    C  += (long)blockIdx.z * strideC;

    __shared__ float As[BK][BM];
    __shared__ float Bs[BK][BN];

    const int tid  = threadIdx.x;
    const int row0 = blockIdx.y * BM;
    const int col0 = blockIdx.x * BN;

    const int aRow  = tid >> 1;
    const int aCol4 = (tid & 1) * 4;
    // B tile: 128 N-rows x 8 K-cols -> float4 along K, scatter-transpose into Bs
    const int bRow  = tid >> 1;          // 0..127 (N index within tile)
    const int bCol4 = (tid & 1) * 4;     // 0 or 4 (K index within tile)

    const int tx = tid & 15;
    const int ty = tid >> 4;

    float acc[TM][TN] = {};
    float ar[TM], br[TN];

    for (int k0 = 0; k0 < K; k0 += BK) {
        float4 av = *(const float4*)(A + (long)(row0 + aRow) * K + k0 + aCol4);
        As[aCol4 + 0][aRow] = av.x;
        As[aCol4 + 1][aRow] = av.y;
        As[aCol4 + 2][aRow] = av.z;
        As[aCol4 + 3][aRow] = av.w;
        float4 bv = *(const float4*)(Bm + (long)(col0 + bRow) * K + k0 + bCol4);
        Bs[bCol4 + 0][bRow] = bv.x;
        Bs[bCol4 + 1][bRow] = bv.y;
        Bs[bCol4 + 2][bRow] = bv.z;
        Bs[bCol4 + 3][bRow] = bv.w;
        __syncthreads();

        #pragma unroll
        for (int k = 0; k < BK; k++) {
            #pragma unroll
            for (int i = 0; i < TM; i++) ar[i] = As[k][ty * TM + i];
            #pragma unroll
            for (int j = 0; j < TN; j++) br[j] = Bs[k][tx * TN + j];
            #pragma unroll
            for (int i = 0; i < TM; i++)
                #pragma unroll
                for (int j = 0; j < TN; j++)
                    acc[i][j] = fmaf(ar[i], br[j], acc[i][j]);
        }
        __syncthreads();
    }

    #pragma unroll
    for (int i = 0; i < TM; i++) {
        const int r = row0 + ty * TM + i;
        #pragma unroll
        for (int j = 0; j < TN; j += 4) {
            const int c = col0 + tx * TN + j;
            float4 v;
            v.x = alpha * acc[i][j + 0];
            v.y = alpha * acc[i][j + 1];
            v.z = alpha * acc[i][j + 2];
            v.w = alpha * acc[i][j + 3];
            *(float4*)(C + (long)r * N + c) = v;
        }
    }
}

// ---------------------------------------------------------------------------
// Row softmax over SEQ=2048 columns. One block (256 threads) per row.
// ---------------------------------------------------------------------------
__global__ __launch_bounds__(256)
void softmax2048(float* __restrict__ data)
{
    const int COLS = SEQ;
    float* p = data + (long)blockIdx.x * COLS;
    const int tid = threadIdx.x;

    float v[8];
    float mx = -1e30f;
    #pragma unroll
    for (int i = 0; i < 8; i++) {
        v[i] = p[tid + i * 256];
        mx = fmaxf(mx, v[i]);
    }
    #pragma unroll
    for (int o = 16; o; o >>= 1)
        mx = fmaxf(mx, __shfl_xor_sync(0xffffffffu, mx, o));

    __shared__ float red[8];
    if ((tid & 31) == 0) red[tid >> 5] = mx;
    __syncthreads();
    mx = red[0];
    #pragma unroll
    for (int w = 1; w < 8; w++) mx = fmaxf(mx, red[w]);

    float s = 0.f;
    #pragma unroll
    for (int i = 0; i < 8; i++) {
        v[i] = __expf(v[i] - mx);
        s += v[i];
    }
    #pragma unroll
    for (int o = 16; o; o >>= 1)
        s += __shfl_xor_sync(0xffffffffu, s, o);
    __syncthreads();
    if ((tid & 31) == 0) red[tid >> 5] = s;
    __syncthreads();
    s = red[0];
    #pragma unroll
    for (int w = 1; w < 8; w++) s += red[w];

    const float inv = 1.0f / s;
    #pragma unroll
    for (int i = 0; i < 8; i++)
        p[tid + i * 256] = v[i] * inv;
}

// ---------------------------------------------------------------------------
// Launch
// ---------------------------------------------------------------------------
extern "C" void kernel_launch(void* const* d_in, const int* in_sizes, int n_in,
                              void* d_out, int out_size)
{
    const float* x  = (const float*)d_in[0];
    const float* Wq = (const float*)d_in[1];
    const float* bq = (const float*)d_in[2];
    const float* Wk = (const float*)d_in[3];
    const float* bk = (const float*)d_in[4];
    const float* Wv = (const float*)d_in[5];
    const float* bv = (const float*)d_in[6];
    float* out = (float*)d_out;

    float *q, *k, *v, *sim;
    cudaGetSymbolAddress((void**)&q,   g_q);
    cudaGetSymbolAddress((void**)&k,   g_k);
    cudaGetSymbolAddress((void**)&v,   g_v);
    cudaGetSymbolAddress((void**)&sim, g_sim);

    // 1) QKV projections: [32768,512] = x[32768,512] @ W[512,512] + b
    {
        dim3 grid(DIM / BN, MROWS / BM, 1);
        sgemm_nn<<<grid, NTHREADS>>>(x, Wq, bq, q, MROWS, DIM, DIM, 0, 0, 0);
        sgemm_nn<<<grid, NTHREADS>>>(x, Wk, bk, k, MROWS, DIM, DIM, 0, 0, 0);
        sgemm_nn<<<grid, NTHREADS>>>(x, Wv, bv, v, MROWS, DIM, DIM, 0, 0, 0);
    }

    // 2) sim[b] = Q[b] @ K[b]^T * (1/8)   [2048,2048] per batch
    {
        dim3 grid(SEQ / BN, SEQ / BM, BATCH);
        sgemm_nt<<<grid, NTHREADS>>>(q, k, sim, SEQ, SEQ, DIM, SCALE,
                                     (long)SEQ * DIM, (long)SEQ * DIM,
                                     (long)SEQ * SEQ);
    }

    // 3) softmax over last dim
    softmax2048<<<MROWS, 256>>>(sim);

    // 4) out[b] = attn[b] @ V[b]   [2048,512] per batch
    {
        dim3 grid(DIM / BN, SEQ / BM, BATCH);
        sgemm_nn<<<grid, NTHREADS>>>(sim, v, nullptr, out, SEQ, DIM, SEQ,
                                     (long)SEQ * SEQ, (long)SEQ * DIM,
                                     (long)SEQ * DIM);
    }
}

// round 3
// speedup vs baseline: 1.3695x; 1.3695x over previous
#include <cuda_runtime.h>
#include <math.h>

// Problem constants
#define BATCH 16
#define SEQ   2048
#define DIM   512
#define MROWS (BATCH * SEQ)   // 32768
#define SCALE 0.125f

// GEMM tile config
#define BM 128
#define BN 128
#define BK 16
#define NTH 256              // 8 warps: 2 (M) x 4 (N), each warp 64x32

#define ASTRIDE 20           // As[m][k], pad 16->20: conflict-free frag loads
#define BSTRIDE_NN 136       // Bs[k][n], pad 128->136: conflict-free
#define BSTRIDE_NT 20        // Bs[n][k], same as A side

// ---------------------------------------------------------------------------
// Scratch (device globals — no allocation allowed)
// ---------------------------------------------------------------------------
__device__ float g_q[(long)MROWS * DIM];
__device__ float g_k[(long)MROWS * DIM];
__device__ float g_v[(long)MROWS * DIM];
__device__ float g_sim[(long)BATCH * SEQ * SEQ];

__device__ __forceinline__ unsigned f2tf32(float f) {
    unsigned r;
    asm("cvt.rna.tf32.f32 %0, %1;" : "=r"(r) : "f"(f));
    return r;
}
// split a into hi (tf32) + lo (tf32 of residual)
__device__ __forceinline__ void tf32split(float a, unsigned &hi, unsigned &lo) {
    hi = f2tf32(a);
    lo = f2tf32(a - __uint_as_float(hi));
}

#define MMA_TF32(ACC, AF0, AF1, AF2, AF3, BF0, BF1)                          \
    asm volatile(                                                            \
        "mma.sync.aligned.m16n8k8.row.col.f32.tf32.tf32.f32 "               \
        "{%0,%1,%2,%3}, {%4,%5,%6,%7}, {%8,%9}, {%0,%1,%2,%3};"             \
        : "+f"(ACC[0]), "+f"(ACC[1]), "+f"(ACC[2]), "+f"(ACC[3])            \
        : "r"(AF0), "r"(AF1), "r"(AF2), "r"(AF3), "r"(BF0), "r"(BF1))

// ---------------------------------------------------------------------------
// TF32x3 tensor-core GEMM (fp32-accurate via hi/lo split).
//   BTRANS=0: C = alpha * A[M,K] * B[K,N]   (+bias)
//   BTRANS=1: C = alpha * A[M,K] * B[N,K]^T (+bias)
// M%128==0, N%128==0, K%16==0. Batched via blockIdx.z.
// ---------------------------------------------------------------------------
template <int BTRANS>
__global__ __launch_bounds__(NTH)
void mma_gemm(const float* __restrict__ A, const float* __restrict__ B,
              const float* __restrict__ bias, float* __restrict__ C,
              int M, int N, int K, float alpha,
              long sA, long sB, long sC)
{
    A += (long)blockIdx.z * sA;
    B += (long)blockIdx.z * sB;
    C += (long)blockIdx.z * sC;

    __shared__ unsigned AsH[BM * ASTRIDE];   // 10 KB
    __shared__ unsigned AsL[BM * ASTRIDE];   // 10 KB
    __shared__ unsigned BsH[BM * ASTRIDE];   // 10 KB (covers both layouts:
    __shared__ unsigned BsL[BM * ASTRIDE];   //  NN needs 16*136=2176 < 2560)

    const int tid  = threadIdx.x;
    const int row0 = blockIdx.y * BM;
    const int col0 = blockIdx.x * BN;

    const int warp = tid >> 5;
    const int lane = tid & 31;
    const int wm   = warp & 1;        // 0..1
    const int wn   = warp >> 1;       // 0..3
    const int g    = lane >> 2;       // 0..7
    const int t4   = lane & 3;        // 0..3

    float acc[4][4][4] = {};

    for (int k0 = 0; k0 < K; k0 += BK) {
        // ---- A tile -> AsH/AsL [m][k] ----
        {
            const int mb = tid >> 2;         // 0..63
            const int kq = (tid & 3) * 4;    // 0..12
            #pragma unroll
            for (int i = 0; i < 2; i++) {
                const int m = mb + 64 * i;
                float4 v = *(const float4*)(A + (long)(row0 + m) * K + k0 + kq);
                uint4 h, l;
                tf32split(v.x, h.x, l.x); tf32split(v.y, h.y, l.y);
                tf32split(v.z, h.z, l.z); tf32split(v.w, h.w, l.w);
                *(uint4*)&AsH[m * ASTRIDE + kq] = h;
                *(uint4*)&AsL[m * ASTRIDE + kq] = l;
            }
        }
        // ---- B tile ----
        if (BTRANS == 0) {
            const int kb = tid >> 5;          // 0..7
            const int n4 = (tid & 31) * 4;    // 0..124
            #pragma unroll
            for (int i = 0; i < 2; i++) {
                const int k = kb + 8 * i;
                float4 v = *(const float4*)(B + (long)(k0 + k) * N + col0 + n4);
                uint4 h, l;
                tf32split(v.x, h.x, l.x); tf32split(v.y, h.y, l.y);
                tf32split(v.z, h.z, l.z); tf32split(v.w, h.w, l.w);
                *(uint4*)&BsH[k * BSTRIDE_NN + n4] = h;
                *(uint4*)&BsL[k * BSTRIDE_NN + n4] = l;
            }
        } else {
            const int nb = tid >> 2;
            const int kq = (tid & 3) * 4;
            #pragma unroll
            for (int i = 0; i < 2; i++) {
                const int n = nb + 64 * i;
                float4 v = *(const float4*)(B + (long)(col0 + n) * K + k0 + kq);
                uint4 h, l;
                tf32split(v.x, h.x, l.x); tf32split(v.y, h.y, l.y);
                tf32split(v.z, h.z, l.z); tf32split(v.w, h.w, l.w);
                *(uint4*)&BsH[n * BSTRIDE_NT + kq] = h;
                *(uint4*)&BsL[n * BSTRIDE_NT + kq] = l;
            }
        }
        __syncthreads();

        // ---- compute: 2 k-steps of m16n8k8, x3 products ----
        #pragma unroll
        for (int ks = 0; ks < 2; ks++) {
            const int kk = ks * 8;

            unsigned afH[4][4], afL[4][4];
            #pragma unroll
            for (int mt = 0; mt < 4; mt++) {
                const int m = wm * 64 + mt * 16 + g;
                const int i0 = m * ASTRIDE + kk + t4;
                const int i1 = (m + 8) * ASTRIDE + kk + t4;
                afH[mt][0] = AsH[i0];     afL[mt][0] = AsL[i0];
                afH[mt][1] = AsH[i1];     afL[mt][1] = AsL[i1];
                afH[mt][2] = AsH[i0 + 4]; afL[mt][2] = AsL[i0 + 4];
                afH[mt][3] = AsH[i1 + 4]; afL[mt][3] = AsL[i1 + 4];
            }

            unsigned bfH[4][2], bfL[4][2];
            #pragma unroll
            for (int nt = 0; nt < 4; nt++) {
                const int n = wn * 32 + nt * 8 + g;
                if (BTRANS == 0) {
                    const int j0 = (kk + t4) * BSTRIDE_NN + n;
                    const int j1 = (kk + t4 + 4) * BSTRIDE_NN + n;
                    bfH[nt][0] = BsH[j0]; bfL[nt][0] = BsL[j0];
                    bfH[nt][1] = BsH[j1]; bfL[nt][1] = BsL[j1];
                } else {
                    const int j0 = n * BSTRIDE_NT + kk + t4;
                    bfH[nt][0] = BsH[j0];     bfL[nt][0] = BsL[j0];
                    bfH[nt][1] = BsH[j0 + 4]; bfL[nt][1] = BsL[j0 + 4];
                }
            }

            #pragma unroll
            for (int mt = 0; mt < 4; mt++)
                #pragma unroll
                for (int nt = 0; nt < 4; nt++) {
                    // lo*hi + hi*lo + hi*hi
                    MMA_TF32(acc[mt][nt],
                             afL[mt][0], afL[mt][1], afL[mt][2], afL[mt][3],
                             bfH[nt][0], bfH[nt][1]);
                    MMA_TF32(acc[mt][nt],
                             afH[mt][0], afH[mt][1], afH[mt][2], afH[mt][3],
                             bfL[nt][0], bfL[nt][1]);
                    MMA_TF32(acc[mt][nt],
                             afH[mt][0], afH[mt][1], afH[mt][2], afH[mt][3],
                             bfH[nt][0], bfH[nt][1]);
                }
        }
        __syncthreads();
    }

    // ---- epilogue ----
    #pragma unroll
    for (int mt = 0; mt < 4; mt++) {
        const int r = row0 + wm * 64 + mt * 16 + g;
        #pragma unroll
        for (int nt = 0; nt < 4; nt++) {
            const int c = col0 + wn * 32 + nt * 8 + 2 * t4;
            float b0 = 0.f, b1 = 0.f;
            if (bias) { b0 = bias[c]; b1 = bias[c + 1]; }
            float2 v0, v1;
            v0.x = alpha * acc[mt][nt][0] + b0;
            v0.y = alpha * acc[mt][nt][1] + b1;
            v1.x = alpha * acc[mt][nt][2] + b0;
            v1.y = alpha * acc[mt][nt][3] + b1;
            *(float2*)(C + (long)r * N + c)       = v0;
            *(float2*)(C + (long)(r + 8) * N + c) = v1;
        }
    }
}

// ---------------------------------------------------------------------------
// Row softmax over SEQ=2048 columns. One block (256 threads) per row.
// ---------------------------------------------------------------------------
__global__ __launch_bounds__(256)
void softmax2048(float* __restrict__ data)
{
    float* p = data + (long)blockIdx.x * SEQ;
    const int tid = threadIdx.x;

    float v[8];
    float mx = -1e30f;
    #pragma unroll
    for (int i = 0; i < 8; i++) {
        v[i] = p[tid + i * 256];
        mx = fmaxf(mx, v[i]);
    }
    #pragma unroll
    for (int o = 16; o; o >>= 1)
        mx = fmaxf(mx, __shfl_xor_sync(0xffffffffu, mx, o));

    __shared__ float red[8];
    if ((tid & 31) == 0) red[tid >> 5] = mx;
    __syncthreads();
    mx = red[0];
    #pragma unroll
    for (int w = 1; w < 8; w++) mx = fmaxf(mx, red[w]);

    float s = 0.f;
    #pragma unroll
    for (int i = 0; i < 8; i++) {
        v[i] = __expf(v[i] - mx);
        s += v[i];
    }
    #pragma unroll
    for (int o = 16; o; o >>= 1)
        s += __shfl_xor_sync(0xffffffffu, s, o);
    __syncthreads();
    if ((tid & 31) == 0) red[tid >> 5] = s;
    __syncthreads();
    s = red[0];
    #pragma unroll
    for (int w = 1; w < 8; w++) s += red[w];

    const float inv = 1.0f / s;
    #pragma unroll
    for (int i = 0; i < 8; i++)
        p[tid + i * 256] = v[i] * inv;
}

// ---------------------------------------------------------------------------
// Launch
// ---------------------------------------------------------------------------
extern "C" void kernel_launch(void* const* d_in, const int* in_sizes, int n_in,
                              void* d_out, int out_size)
{
    const float* x  = (const float*)d_in[0];
    const float* Wq = (const float*)d_in[1];
    const float* bq = (const float*)d_in[2];
    const float* Wk = (const float*)d_in[3];
    const float* bk = (const float*)d_in[4];
    const float* Wv = (const float*)d_in[5];
    const float* bv = (const float*)d_in[6];
    float* out = (float*)d_out;

    float *q, *k, *v, *sim;
    cudaGetSymbolAddress((void**)&q,   g_q);
    cudaGetSymbolAddress((void**)&k,   g_k);
    cudaGetSymbolAddress((void**)&v,   g_v);
    cudaGetSymbolAddress((void**)&sim, g_sim);

    // 1) QKV projections: [32768,512] = x @ W + b  (NN)
    {
        dim3 grid(DIM / BN, MROWS / BM, 1);
        mma_gemm<0><<<grid, NTH>>>(x, Wq, bq, q, MROWS, DIM, DIM, 1.0f, 0, 0, 0);
        mma_gemm<0><<<grid, NTH>>>(x, Wk, bk, k, MROWS, DIM, DIM, 1.0f, 0, 0, 0);
        mma_gemm<0><<<grid, NTH>>>(x, Wv, bv, v, MROWS, DIM, DIM, 1.0f, 0, 0, 0);
    }

    // 2) sim[b] = Q[b] @ K[b]^T * (1/8)  (NT)
    {
        dim3 grid(SEQ / BN, SEQ / BM, BATCH);
        mma_gemm<1><<<grid, NTH>>>(q, k, nullptr, sim, SEQ, SEQ, DIM, SCALE,
                                   (long)SEQ * DIM, (long)SEQ * DIM,
                                   (long)SEQ * SEQ);
    }

    // 3) softmax over last dim
    softmax2048<<<MROWS, 256>>>(sim);

    // 4) out[b] = attn[b] @ V[b]  (NN)
    {
        dim3 grid(DIM / BN, SEQ / BM, BATCH);
        mma_gemm<0><<<grid, NTH>>>(sim, v, nullptr, out, SEQ, DIM, SEQ, 1.0f,
                                   (long)SEQ * SEQ, (long)SEQ * DIM,
                                   (long)SEQ * DIM);
    }
}

// round 4
// speedup vs baseline: 2.2228x; 1.6231x over previous
#include <cuda_runtime.h>
#include <cuda_fp16.h>
#include <math.h>

// Problem constants
#define BATCH 16
#define SEQ   2048
#define DIM   512
#define MROWS (BATCH * SEQ)   // 32768
#define SCALE 0.125f

// GEMM tile config
#define BM 128
#define BN 128
#define BK 32
#define NTH 256              // 8 warps: 2 (M) x 4 (N), each warp 64x32

#define SROW 40              // half-stride per row (32 + 8 pad) -> conflict-free
#define TILE_HALFS (BM * SROW)           // 5120 halves per array
#define STAGE_HALFS (4 * TILE_HALFS)     // AsH, AsL, BsH, BsL
#define SMEM_BYTES (2 * STAGE_HALFS * 2) // 2 stages * halves * 2B = 81920

// ---------------------------------------------------------------------------
// Scratch (device globals — no allocation allowed)
// ---------------------------------------------------------------------------
__device__ float g_q[(long)MROWS * DIM];
__device__ float g_k[(long)MROWS * DIM];
__device__ float g_v[(long)MROWS * DIM];
__device__ float g_vt[(long)MROWS * DIM];
__device__ float g_wt[3L * DIM * DIM];
__device__ float g_sim[(long)BATCH * SEQ * SEQ];

// ---------------------------------------------------------------------------
// fp16 hi/lo split helpers
// ---------------------------------------------------------------------------
__device__ __forceinline__ void split2(float a, float b, unsigned &h, unsigned &l) {
    __half2 hh = __floats2half2_rn(a, b);
    float2 r = __half22float2(hh);
    __half2 ll = __floats2half2_rn(a - r.x, b - r.y);
    h = *(unsigned*)&hh;
    l = *(unsigned*)&ll;
}

#define MMA_F16(ACC, A0, A1, A2, A3, B0, B1)                                  \
    asm volatile(                                                             \
        "mma.sync.aligned.m16n8k16.row.col.f32.f16.f16.f32 "                 \
        "{%0,%1,%2,%3}, {%4,%5,%6,%7}, {%8,%9}, {%0,%1,%2,%3};"              \
        : "+f"(ACC[0]), "+f"(ACC[1]), "+f"(ACC[2]), "+f"(ACC[3])             \
        : "r"(A0), "r"(A1), "r"(A2), "r"(A3), "r"(B0), "r"(B1))

// ---------------------------------------------------------------------------
// fp16x3 NT GEMM: C[M,N] = alpha * A[M,K] * B[N,K]^T + bias
// M%128==0, N%128==0, K%32==0. Batched via blockIdx.z.
// 2-stage smem double buffering, dynamic smem.
// ---------------------------------------------------------------------------
__global__ __launch_bounds__(NTH, 1)
void gemm_nt_f16x3(const float* __restrict__ A, const float* __restrict__ B,
                   const float* __restrict__ bias, float* __restrict__ C,
                   int M, int N, int K, float alpha,
                   long sA, long sB, long sC)
{
    extern __shared__ __align__(16) __half dyn[];

    A += (long)blockIdx.z * sA;
    B += (long)blockIdx.z * sB;
    C += (long)blockIdx.z * sC;

    const int tid  = threadIdx.x;
    const int row0 = blockIdx.y * BM;
    const int col0 = blockIdx.x * BN;

    const int warp = tid >> 5;
    const int lane = tid & 31;
    const int wm   = warp & 1;
    const int wn   = warp >> 1;
    const int g    = lane >> 2;
    const int t4   = lane & 3;

    // loader mapping: 128 rows x 32 k-floats, each thread 4x float4
    const int lrow = tid >> 1;              // 0..127
    const int lk0  = (tid & 1) * 16;        // 0 or 16

    const float* Aload = A + (long)(row0 + lrow) * K + lk0;
    const float* Bload = B + (long)(col0 + lrow) * K + lk0;

    float acc[4][4][4] = {};
    float4 aReg[4], bReg[4];

    const int NIT = K / BK;

    // ---------------- helpers as macros -----------------
#define LOAD_REGS(IT)                                                         \
    {                                                                         \
        const long kb = (long)(IT) * BK;                                      \
        _Pragma("unroll")                                                     \
        for (int i = 0; i < 4; i++) {                                         \
            aReg[i] = *(const float4*)(Aload + kb + 4 * i);                   \
            bReg[i] = *(const float4*)(Bload + kb + 4 * i);                   \
        }                                                                     \
    }

#define CVT_STORE(STG)                                                        \
    {                                                                         \
        __half* aH = dyn + (STG) * STAGE_HALFS;                               \
        __half* aL = aH + TILE_HALFS;                                         \
        __half* bH = aL + TILE_HALFS;                                         \
        __half* bL = bH + TILE_HALFS;                                         \
        const int base = lrow * SROW + lk0;                                   \
        _Pragma("unroll")                                                     \
        for (int i = 0; i < 4; i++) {                                         \
            uint2 h, l;                                                       \
            split2(aReg[i].x, aReg[i].y, h.x, l.x);                           \
            split2(aReg[i].z, aReg[i].w, h.y, l.y);                           \
            *(uint2*)&aH[base + 4 * i] = h;                                   \
            *(uint2*)&aL[base + 4 * i] = l;                                   \
            split2(bReg[i].x, bReg[i].y, h.x, l.x);                           \
            split2(bReg[i].z, bReg[i].w, h.y, l.y);                           \
            *(uint2*)&bH[base + 4 * i] = h;                                   \
            *(uint2*)&bL[base + 4 * i] = l;                                   \
        }                                                                     \
    }

    // prologue
    LOAD_REGS(0);
    CVT_STORE(0);
    __syncthreads();

    int cur = 0;
    for (int it = 0; it < NIT; it++) {
        const bool more = (it + 1 < NIT);
        if (more) LOAD_REGS(it + 1);

        const __half* aH = dyn + cur * STAGE_HALFS;
        const __half* aL = aH + TILE_HALFS;
        const __half* bH = aL + TILE_HALFS;
        const __half* bL = bH + TILE_HALFS;

        #pragma unroll
        for (int ks = 0; ks < 2; ks++) {
            const int kk = ks * 16;

            unsigned afH[4][4], afL[4][4];
            #pragma unroll
            for (int mt = 0; mt < 4; mt++) {
                const int m = wm * 64 + mt * 16 + g;
                const int i0 = m * SROW + kk + 2 * t4;
                const int i1 = (m + 8) * SROW + kk + 2 * t4;
                afH[mt][0] = *(const unsigned*)&aH[i0];
                afH[mt][1] = *(const unsigned*)&aH[i1];
                afH[mt][2] = *(const unsigned*)&aH[i0 + 8];
                afH[mt][3] = *(const unsigned*)&aH[i1 + 8];
                afL[mt][0] = *(const unsigned*)&aL[i0];
                afL[mt][1] = *(const unsigned*)&aL[i1];
                afL[mt][2] = *(const unsigned*)&aL[i0 + 8];
                afL[mt][3] = *(const unsigned*)&aL[i1 + 8];
            }

            unsigned bfH[4][2], bfL[4][2];
            #pragma unroll
            for (int nt = 0; nt < 4; nt++) {
                const int n = wn * 32 + nt * 8 + g;
                const int j0 = n * SROW + kk + 2 * t4;
                bfH[nt][0] = *(const unsigned*)&bH[j0];
                bfH[nt][1] = *(const unsigned*)&bH[j0 + 8];
                bfL[nt][0] = *(const unsigned*)&bL[j0];
                bfL[nt][1] = *(const unsigned*)&bL[j0 + 8];
            }

            #pragma unroll
            for (int mt = 0; mt < 4; mt++)
                #pragma unroll
                for (int nt = 0; nt < 4; nt++) {
                    MMA_F16(acc[mt][nt],
                            afL[mt][0], afL[mt][1], afL[mt][2], afL[mt][3],
                            bfH[nt][0], bfH[nt][1]);
                    MMA_F16(acc[mt][nt],
                            afH[mt][0], afH[mt][1], afH[mt][2], afH[mt][3],
                            bfL[nt][0], bfL[nt][1]);
                    MMA_F16(acc[mt][nt],
                            afH[mt][0], afH[mt][1], afH[mt][2], afH[mt][3],
                            bfH[nt][0], bfH[nt][1]);
                }
        }

        if (more) CVT_STORE(cur ^ 1);
        __syncthreads();
        cur ^= 1;
    }

    // ---- epilogue ----
    #pragma unroll
    for (int mt = 0; mt < 4; mt++) {
        const int r = row0 + wm * 64 + mt * 16 + g;
        #pragma unroll
        for (int nt = 0; nt < 4; nt++) {
            const int c = col0 + wn * 32 + nt * 8 + 2 * t4;
            float b0 = 0.f, b1 = 0.f;
            if (bias) { b0 = bias[c]; b1 = bias[c + 1]; }
            float2 v0, v1;
            v0.x = alpha * acc[mt][nt][0] + b0;
            v0.y = alpha * acc[mt][nt][1] + b1;
            v1.x = alpha * acc[mt][nt][2] + b0;
            v1.y = alpha * acc[mt][nt][3] + b1;
            *(float2*)(C + (long)r * N + c)       = v0;
            *(float2*)(C + (long)(r + 8) * N + c) = v1;
        }
    }
#undef LOAD_REGS
#undef CVT_STORE
}

// ---------------------------------------------------------------------------
// 32x32 tiled transpose: out[C,R] = in[R,C]^T. Batched via blockIdx.z.
// ---------------------------------------------------------------------------
__global__ __launch_bounds__(256)
void transpose_k(const float* __restrict__ in, float* __restrict__ out,
                 int R, int C, long sIn, long sOut)
{
    __shared__ float t[32][33];
    in  += (long)blockIdx.z * sIn;
    out += (long)blockIdx.z * sOut;
    const int tx = threadIdx.x & 31;
    const int ty = threadIdx.x >> 5;      // 0..7
    const int bx = blockIdx.x * 32;       // col base (in)
    const int by = blockIdx.y * 32;       // row base (in)
    #pragma unroll
    for (int j = 0; j < 4; j++)
        t[ty + 8 * j][tx] = in[(long)(by + ty + 8 * j) * C + bx + tx];
    __syncthreads();
    #pragma unroll
    for (int j = 0; j < 4; j++)
        out[(long)(bx + ty + 8 * j) * R + by + tx] = t[tx][ty + 8 * j];
}

// ---------------------------------------------------------------------------
// Row softmax over SEQ=2048 columns. One block (256 threads) per row.
// ---------------------------------------------------------------------------
__global__ __launch_bounds__(256)
void softmax2048(float* __restrict__ data)
{
    float* p = data + (long)blockIdx.x * SEQ;
    const int tid = threadIdx.x;

    float v[8];
    float mx = -1e30f;
    #pragma unroll
    for (int i = 0; i < 8; i++) {
        v[i] = p[tid + i * 256];
        mx = fmaxf(mx, v[i]);
    }
    #pragma unroll
    for (int o = 16; o; o >>= 1)
        mx = fmaxf(mx, __shfl_xor_sync(0xffffffffu, mx, o));

    __shared__ float red[8];
    if ((tid & 31) == 0) red[tid >> 5] = mx;
    __syncthreads();
    mx = red[0];
    #pragma unroll
    for (int w = 1; w < 8; w++) mx = fmaxf(mx, red[w]);

    float s = 0.f;
    #pragma unroll
    for (int i = 0; i < 8; i++) {
        v[i] = __expf(v[i] - mx);
        s += v[i];
    }
    #pragma unroll
    for (int o = 16; o; o >>= 1)
        s += __shfl_xor_sync(0xffffffffu, s, o);
    __syncthreads();
    if ((tid & 31) == 0) red[tid >> 5] = s;
    __syncthreads();
    s = red[0];
    #pragma unroll
    for (int w = 1; w < 8; w++) s += red[w];

    const float inv = 1.0f / s;
    #pragma unroll
    for (int i = 0; i < 8; i++)
        p[tid + i * 256] = v[i] * inv;
}

// ---------------------------------------------------------------------------
// Launch
// ---------------------------------------------------------------------------
extern "C" void kernel_launch(void* const* d_in, const int* in_sizes, int n_in,
                              void* d_out, int out_size)
{
    const float* x  = (const float*)d_in[0];
    const float* Wq = (const float*)d_in[1];
    const float* bq = (const float*)d_in[2];
    const float* Wk = (const float*)d_in[3];
    const float* bk = (const float*)d_in[4];
    const float* Wv = (const float*)d_in[5];
    const float* bv = (const float*)d_in[6];
    float* out = (float*)d_out;

    float *q, *k, *v, *vt, *wt, *sim;
    cudaGetSymbolAddress((void**)&q,   g_q);
    cudaGetSymbolAddress((void**)&k,   g_k);
    cudaGetSymbolAddress((void**)&v,   g_v);
    cudaGetSymbolAddress((void**)&vt,  g_vt);
    cudaGetSymbolAddress((void**)&wt,  g_wt);
    cudaGetSymbolAddress((void**)&sim, g_sim);

    cudaFuncSetAttribute(gemm_nt_f16x3,
                         cudaFuncAttributeMaxDynamicSharedMemorySize,
                         SMEM_BYTES);

    float* Wqt = wt;
    float* Wkt = wt + (long)DIM * DIM;
    float* Wvt = wt + 2L * DIM * DIM;

    // 0) transpose weights: Wt[n][k] = W[k][n]
    {
        dim3 grid(DIM / 32, DIM / 32, 1);
        transpose_k<<<grid, 256>>>(Wq, Wqt, DIM, DIM, 0, 0);
        transpose_k<<<grid, 256>>>(Wk, Wkt, DIM, DIM, 0, 0);
        transpose_k<<<grid, 256>>>(Wv, Wvt, DIM, DIM, 0, 0);
    }

    // 1) QKV projections (NT vs transposed weights)
    {
        dim3 grid(DIM / BN, MROWS / BM, 1);
        gemm_nt_f16x3<<<grid, NTH, SMEM_BYTES>>>(x, Wqt, bq, q,
                                                 MROWS, DIM, DIM, 1.0f, 0, 0, 0);
        gemm_nt_f16x3<<<grid, NTH, SMEM_BYTES>>>(x, Wkt, bk, k,
                                                 MROWS, DIM, DIM, 1.0f, 0, 0, 0);
        gemm_nt_f16x3<<<grid, NTH, SMEM_BYTES>>>(x, Wvt, bv, v,
                                                 MROWS, DIM, DIM, 1.0f, 0, 0, 0);
    }

    // 1b) transpose V per batch: vt[b][d][s] = v[b][s][d]
    {
        dim3 grid(DIM / 32, SEQ / 32, BATCH);
        transpose_k<<<grid, 256>>>(v, vt, SEQ, DIM,
                                   (long)SEQ * DIM, (long)SEQ * DIM);
    }

    // 2) sim[b] = Q[b] @ K[b]^T * (1/8)  (NT natural)
    {
        dim3 grid(SEQ / BN, SEQ / BM, BATCH);
        gemm_nt_f16x3<<<grid, NTH, SMEM_BYTES>>>(q, k, nullptr, sim,
                                                 SEQ, SEQ, DIM, SCALE,
                                                 (long)SEQ * DIM,
                                                 (long)SEQ * DIM,
                                                 (long)SEQ * SEQ);
    }

    // 3) softmax over last dim
    softmax2048<<<MROWS, 256>>>(sim);

    // 4) out[b] = attn[b] @ V[b] = attn[b] @ (Vt[b])^T  (NT)
    {
        dim3 grid(DIM / BN, SEQ / BM, BATCH);
        gemm_nt_f16x3<<<grid, NTH, SMEM_BYTES>>>(sim, vt, nullptr, out,
                                                 SEQ, DIM, SEQ, 1.0f,
                                                 (long)SEQ * SEQ,
                                                 (long)SEQ * DIM,
                                                 (long)SEQ * DIM);
    }
}

// round 5
// speedup vs baseline: 2.3204x; 1.0439x over previous
#include <cuda_runtime.h>
#include <cuda_fp16.h>
#include <math.h>

// Problem constants
#define BATCH 16
#define SEQ   2048
#define DIM   512
#define MROWS (BATCH * SEQ)   // 32768
#define SCALE 0.125f

// GEMM tile config
#define BM 128
#define BN 256
#define BK 32
#define NTH 256              // 8 warps: 2 (M) x 4 (N), each warp 64x64

#define SROW 40              // half-stride per row (32 + 8 pad) -> conflict-free
#define A_HALFS (BM * SROW)              // 5120
#define B_HALFS (BN * SROW)              // 10240
#define STAGE_HALFS (2 * (A_HALFS + B_HALFS))  // aH,aL,bH,bL = 30720
#define SMEM_BYTES (2 * STAGE_HALFS * 2)       // 2 stages -> 122880 B

// ---------------------------------------------------------------------------
// Scratch (device globals — no allocation allowed)
// ---------------------------------------------------------------------------
__device__ float g_q[(long)MROWS * DIM];
__device__ float g_k[(long)MROWS * DIM];
__device__ float g_v[(long)MROWS * DIM];
__device__ float g_vt[(long)MROWS * DIM];
__device__ float g_wt[3L * DIM * DIM];
__device__ float g_sim[(long)BATCH * SEQ * SEQ];

// ---------------------------------------------------------------------------
// fp16 hi/lo split helpers
// ---------------------------------------------------------------------------
__device__ __forceinline__ void split2(float a, float b, unsigned &h, unsigned &l) {
    __half2 hh = __floats2half2_rn(a, b);
    float2 r = __half22float2(hh);
    __half2 ll = __floats2half2_rn(a - r.x, b - r.y);
    h = *(unsigned*)&hh;
    l = *(unsigned*)&ll;
}

#define MMA_F16(ACC, A0, A1, A2, A3, B0, B1)                                  \
    asm volatile(                                                             \
        "mma.sync.aligned.m16n8k16.row.col.f32.f16.f16.f32 "                 \
        "{%0,%1,%2,%3}, {%4,%5,%6,%7}, {%8,%9}, {%0,%1,%2,%3};"              \
        : "+f"(ACC[0]), "+f"(ACC[1]), "+f"(ACC[2]), "+f"(ACC[3])             \
        : "r"(A0), "r"(A1), "r"(A2), "r"(A3), "r"(B0), "r"(B1))

// ---------------------------------------------------------------------------
// fp16x3 NT GEMM: C[M,N] = alpha * A[M,K] * B[N,K]^T + bias
// M%128==0, N%256==0, K%32==0. Batched via blockIdx.z.
// ---------------------------------------------------------------------------
__global__ __launch_bounds__(NTH, 1)
void gemm_nt_f16x3(const float* __restrict__ A, const float* __restrict__ B,
                   const float* __restrict__ bias, float* __restrict__ C,
                   int M, int N, int K, float alpha,
                   long sA, long sB, long sC)
{
    extern __shared__ __align__(16) __half dyn[];

    A += (long)blockIdx.z * sA;
    B += (long)blockIdx.z * sB;
    C += (long)blockIdx.z * sC;

    const int tid  = threadIdx.x;
    const int row0 = blockIdx.y * BM;
    const int col0 = blockIdx.x * BN;

    const int warp = tid >> 5;
    const int lane = tid & 31;
    const int wm   = warp & 1;        // 0..1 (64-row slab)
    const int wn   = warp >> 1;       // 0..3 (64-col slab)
    const int g    = lane >> 2;       // 0..7
    const int t4   = lane & 3;        // 0..3

    // A loader: 128 rows, 2 threads/row, each 16 k-floats (4 float4)
    const int alrow = tid >> 1;
    const int alk0  = (tid & 1) * 16;
    const float* Aload = A + (long)(row0 + alrow) * K + alk0;
    // B loader: 256 rows, 1 thread/row, 32 k-floats (8 float4)
    const float* Bload = B + (long)(col0 + tid) * K;

    float acc[4][8][4] = {};          // [mt][nt][4]
    float4 aReg[4], bReg[8];

    const int NIT = K / BK;

#define LOAD_REGS(IT)                                                         \
    {                                                                         \
        const long kb = (long)(IT) * BK;                                      \
        _Pragma("unroll")                                                     \
        for (int i = 0; i < 4; i++)                                           \
            aReg[i] = *(const float4*)(Aload + kb + 4 * i);                   \
        _Pragma("unroll")                                                     \
        for (int i = 0; i < 8; i++)                                           \
            bReg[i] = *(const float4*)(Bload + kb + 4 * i);                   \
    }

#define CVT_STORE(STG)                                                        \
    {                                                                         \
        __half* aH = dyn + (STG) * STAGE_HALFS;                               \
        __half* aL = aH + A_HALFS;                                            \
        __half* bH = aL + A_HALFS;                                            \
        __half* bL = bH + B_HALFS;                                            \
        const int abase = alrow * SROW + alk0;                                \
        _Pragma("unroll")                                                     \
        for (int i = 0; i < 4; i++) {                                         \
            uint2 h, l;                                                       \
            split2(aReg[i].x, aReg[i].y, h.x, l.x);                           \
            split2(aReg[i].z, aReg[i].w, h.y, l.y);                           \
            *(uint2*)&aH[abase + 4 * i] = h;                                  \
            *(uint2*)&aL[abase + 4 * i] = l;                                  \
        }                                                                     \
        const int bbase = tid * SROW;                                         \
        _Pragma("unroll")                                                     \
        for (int i = 0; i < 8; i++) {                                         \
            uint2 h, l;                                                       \
            split2(bReg[i].x, bReg[i].y, h.x, l.x);                           \
            split2(bReg[i].z, bReg[i].w, h.y, l.y);                           \
            *(uint2*)&bH[bbase + 4 * i] = h;                                  \
            *(uint2*)&bL[bbase + 4 * i] = l;                                  \
        }                                                                     \
    }

    // prologue
    LOAD_REGS(0);
    CVT_STORE(0);
    __syncthreads();

    int cur = 0;
    for (int it = 0; it < NIT; it++) {
        const bool more = (it + 1 < NIT);
        if (more) LOAD_REGS(it + 1);

        const __half* aH = dyn + cur * STAGE_HALFS;
        const __half* aL = aH + A_HALFS;
        const __half* bH = aL + A_HALFS;
        const __half* bL = bH + B_HALFS;

        #pragma unroll
        for (int ks = 0; ks < 2; ks++) {
            const int kk = ks * 16;

            unsigned afH[4][4], afL[4][4];
            #pragma unroll
            for (int mt = 0; mt < 4; mt++) {
                const int m = wm * 64 + mt * 16 + g;
                const int i0 = m * SROW + kk + 2 * t4;
                const int i1 = (m + 8) * SROW + kk + 2 * t4;
                afH[mt][0] = *(const unsigned*)&aH[i0];
                afH[mt][1] = *(const unsigned*)&aH[i1];
                afH[mt][2] = *(const unsigned*)&aH[i0 + 8];
                afH[mt][3] = *(const unsigned*)&aH[i1 + 8];
                afL[mt][0] = *(const unsigned*)&aL[i0];
                afL[mt][1] = *(const unsigned*)&aL[i1];
                afL[mt][2] = *(const unsigned*)&aL[i0 + 8];
                afL[mt][3] = *(const unsigned*)&aL[i1 + 8];
            }

            // B fragments in two quads to bound live registers
            #pragma unroll
            for (int half = 0; half < 2; half++) {
                unsigned bfH[4][2], bfL[4][2];
                #pragma unroll
                for (int q = 0; q < 4; q++) {
                    const int n = wn * 64 + (half * 4 + q) * 8 + g;
                    const int j0 = n * SROW + kk + 2 * t4;
                    bfH[q][0] = *(const unsigned*)&bH[j0];
                    bfH[q][1] = *(const unsigned*)&bH[j0 + 8];
                    bfL[q][0] = *(const unsigned*)&bL[j0];
                    bfL[q][1] = *(const unsigned*)&bL[j0 + 8];
                }
                #pragma unroll
                for (int mt = 0; mt < 4; mt++)
                    #pragma unroll
                    for (int q = 0; q < 4; q++) {
                        float* a4 = acc[mt][half * 4 + q];
                        MMA_F16(a4,
                                afL[mt][0], afL[mt][1], afL[mt][2], afL[mt][3],
                                bfH[q][0], bfH[q][1]);
                        MMA_F16(a4,
                                afH[mt][0], afH[mt][1], afH[mt][2], afH[mt][3],
                                bfL[q][0], bfL[q][1]);
                        MMA_F16(a4,
                                afH[mt][0], afH[mt][1], afH[mt][2], afH[mt][3],
                                bfH[q][0], bfH[q][1]);
                    }
            }
        }

        if (more) CVT_STORE(cur ^ 1);
        __syncthreads();
        cur ^= 1;
    }

    // ---- epilogue ----
    #pragma unroll
    for (int mt = 0; mt < 4; mt++) {
        const int r = row0 + wm * 64 + mt * 16 + g;
        #pragma unroll
        for (int nt = 0; nt < 8; nt++) {
            const int c = col0 + wn * 64 + nt * 8 + 2 * t4;
            float b0 = 0.f, b1 = 0.f;
            if (bias) { b0 = bias[c]; b1 = bias[c + 1]; }
            float2 v0, v1;
            v0.x = alpha * acc[mt][nt][0] + b0;
            v0.y = alpha * acc[mt][nt][1] + b1;
            v1.x = alpha * acc[mt][nt][2] + b0;
            v1.y = alpha * acc[mt][nt][3] + b1;
            *(float2*)(C + (long)r * N + c)       = v0;
            *(float2*)(C + (long)(r + 8) * N + c) = v1;
        }
    }
#undef LOAD_REGS
#undef CVT_STORE
}

// ---------------------------------------------------------------------------
// 32x32 tiled transpose: out[C,R] = in[R,C]^T. Batched via blockIdx.z.
// ---------------------------------------------------------------------------
__global__ __launch_bounds__(256)
void transpose_k(const float* __restrict__ in, float* __restrict__ out,
                 int R, int C, long sIn, long sOut)
{
    __shared__ float t[32][33];
    in  += (long)blockIdx.z * sIn;
    out += (long)blockIdx.z * sOut;
    const int tx = threadIdx.x & 31;
    const int ty = threadIdx.x >> 5;
    const int bx = blockIdx.x * 32;
    const int by = blockIdx.y * 32;
    #pragma unroll
    for (int j = 0; j < 4; j++)
        t[ty + 8 * j][tx] = in[(long)(by + ty + 8 * j) * C + bx + tx];
    __syncthreads();
    #pragma unroll
    for (int j = 0; j < 4; j++)
        out[(long)(bx + ty + 8 * j) * R + by + tx] = t[tx][ty + 8 * j];
}

// ---------------------------------------------------------------------------
// Row softmax over SEQ=2048 columns. One block (256 threads) per row.
// ---------------------------------------------------------------------------
__global__ __launch_bounds__(256)
void softmax2048(float* __restrict__ data)
{
    float* p = data + (long)blockIdx.x * SEQ;
    const int tid = threadIdx.x;

    float v[8];
    float mx = -1e30f;
    #pragma unroll
    for (int i = 0; i < 8; i++) {
        v[i] = p[tid + i * 256];
        mx = fmaxf(mx, v[i]);
    }
    #pragma unroll
    for (int o = 16; o; o >>= 1)
        mx = fmaxf(mx, __shfl_xor_sync(0xffffffffu, mx, o));

    __shared__ float red[8];
    if ((tid & 31) == 0) red[tid >> 5] = mx;
    __syncthreads();
    mx = red[0];
    #pragma unroll
    for (int w = 1; w < 8; w++) mx = fmaxf(mx, red[w]);

    float s = 0.f;
    #pragma unroll
    for (int i = 0; i < 8; i++) {
        v[i] = __expf(v[i] - mx);
        s += v[i];
    }
    #pragma unroll
    for (int o = 16; o; o >>= 1)
        s += __shfl_xor_sync(0xffffffffu, s, o);
    __syncthreads();
    if ((tid & 31) == 0) red[tid >> 5] = s;
    __syncthreads();
    s = red[0];
    #pragma unroll
    for (int w = 1; w < 8; w++) s += red[w];

    const float inv = 1.0f / s;
    #pragma unroll
    for (int i = 0; i < 8; i++)
        p[tid + i * 256] = v[i] * inv;
}

// ---------------------------------------------------------------------------
// Launch
// ---------------------------------------------------------------------------
extern "C" void kernel_launch(void* const* d_in, const int* in_sizes, int n_in,
                              void* d_out, int out_size)
{
    const float* x  = (const float*)d_in[0];
    const float* Wq = (const float*)d_in[1];
    const float* bq = (const float*)d_in[2];
    const float* Wk = (const float*)d_in[3];
    const float* bk = (const float*)d_in[4];
    const float* Wv = (const float*)d_in[5];
    const float* bv = (const float*)d_in[6];
    float* out = (float*)d_out;

    float *q, *k, *v, *vt, *wt, *sim;
    cudaGetSymbolAddress((void**)&q,   g_q);
    cudaGetSymbolAddress((void**)&k,   g_k);
    cudaGetSymbolAddress((void**)&v,   g_v);
    cudaGetSymbolAddress((void**)&vt,  g_vt);
    cudaGetSymbolAddress((void**)&wt,  g_wt);
    cudaGetSymbolAddress((void**)&sim, g_sim);

    cudaFuncSetAttribute(gemm_nt_f16x3,
                         cudaFuncAttributeMaxDynamicSharedMemorySize,
                         SMEM_BYTES);

    float* Wqt = wt;
    float* Wkt = wt + (long)DIM * DIM;
    float* Wvt = wt + 2L * DIM * DIM;

    // 0) transpose weights: Wt[n][k] = W[k][n]
    {
        dim3 grid(DIM / 32, DIM / 32, 1);
        transpose_k<<<grid, 256>>>(Wq, Wqt, DIM, DIM, 0, 0);
        transpose_k<<<grid, 256>>>(Wk, Wkt, DIM, DIM, 0, 0);
        transpose_k<<<grid, 256>>>(Wv, Wvt, DIM, DIM, 0, 0);
    }

    // 1) QKV projections (NT vs transposed weights)
    {
        dim3 grid(DIM / BN, MROWS / BM, 1);
        gemm_nt_f16x3<<<grid, NTH, SMEM_BYTES>>>(x, Wqt, bq, q,
                                                 MROWS, DIM, DIM, 1.0f, 0, 0, 0);
        gemm_nt_f16x3<<<grid, NTH, SMEM_BYTES>>>(x, Wkt, bk, k,
                                                 MROWS, DIM, DIM, 1.0f, 0, 0, 0);
        gemm_nt_f16x3<<<grid, NTH, SMEM_BYTES>>>(x, Wvt, bv, v,
                                                 MROWS, DIM, DIM, 1.0f, 0, 0, 0);
    }

    // 1b) transpose V per batch: vt[b][d][s] = v[b][s][d]
    {
        dim3 grid(DIM / 32, SEQ / 32, BATCH);
        transpose_k<<<grid, 256>>>(v, vt, SEQ, DIM,
                                   (long)SEQ * DIM, (long)SEQ * DIM);
    }

    // 2) sim[b] = Q[b] @ K[b]^T * (1/8)  (NT natural)
    {
        dim3 grid(SEQ / BN, SEQ / BM, BATCH);
        gemm_nt_f16x3<<<grid, NTH, SMEM_BYTES>>>(q, k, nullptr, sim,
                                                 SEQ, SEQ, DIM, SCALE,
                                                 (long)SEQ * DIM,
                                                 (long)SEQ * DIM,
                                                 (long)SEQ * SEQ);
    }

    // 3) softmax over last dim
    softmax2048<<<MROWS, 256>>>(sim);

    // 4) out[b] = attn[b] @ V[b] = attn[b] @ (Vt[b])^T  (NT)
    {
        dim3 grid(DIM / BN, SEQ / BM, BATCH);
        gemm_nt_f16x3<<<grid, NTH, SMEM_BYTES>>>(sim, vt, nullptr, out,
                                                 SEQ, DIM, SEQ, 1.0f,
                                                 (long)SEQ * SEQ,
                                                 (long)SEQ * DIM,
                                                 (long)SEQ * DIM);
    }
}

// round 9
// speedup vs baseline: 2.6703x; 1.1508x over previous
#include <cuda_runtime.h>
#include <cuda_fp16.h>
#include <cstdint>
#include <math.h>

// Problem constants
#define BATCH 16
#define SEQ   2048
#define DIM   512
#define MROWS (BATCH * SEQ)   // 32768
#define SCALE 0.125f

// GEMM tile config: CTA 256x128, BK=32, 512 threads (16 warps, 4x4), warp 64x32
#define BM 256
#define BN 128
#define BK 32
#define NTH 512

#define SROW 40                      // halves per row (32 + 8 pad)
#define O_AH 0
#define O_AL (BM * SROW * 2)         // 20480
#define O_BH (2 * BM * SROW * 2)     // 40960
#define O_BL (O_BH + BN * SROW * 2)  // 51200
#define STAGE_BYTES (O_BL + BN * SROW * 2)   // 61440
#define NSTAGES 3
#define SMEM_BYTES (NSTAGES * STAGE_BYTES)   // 184320

// ---------------------------------------------------------------------------
// Scratch (device globals — no allocation allowed)
// ---------------------------------------------------------------------------
__device__ __half g_xH[(size_t)MROWS * DIM];
__device__ __half g_xL[(size_t)MROWS * DIM];
__device__ __half g_wH[3 * (size_t)DIM * DIM];
__device__ __half g_wL[3 * (size_t)DIM * DIM];
__device__ __half g_qH[(size_t)MROWS * DIM];
__device__ __half g_qL[(size_t)MROWS * DIM];
__device__ __half g_kH[(size_t)MROWS * DIM];
__device__ __half g_kL[(size_t)MROWS * DIM];
__device__ float  g_v [(size_t)MROWS * DIM];
__device__ __half g_vtH[(size_t)MROWS * DIM];
__device__ __half g_vtL[(size_t)MROWS * DIM];
__device__ float  g_sim[(size_t)BATCH * SEQ * SEQ];
__device__ __half g_aH[(size_t)BATCH * SEQ * SEQ];
__device__ __half g_aL[(size_t)BATCH * SEQ * SEQ];

// ---------------------------------------------------------------------------
// Helpers
// ---------------------------------------------------------------------------
__device__ __forceinline__ void split2(float a, float b, unsigned &h, unsigned &l) {
    __half2 hh = __floats2half2_rn(a, b);
    float2 r = __half22float2(hh);
    __half2 ll = __floats2half2_rn(a - r.x, b - r.y);
    h = *(unsigned*)&hh;
    l = *(unsigned*)&ll;
}

__device__ __forceinline__ void cpa16(unsigned dst, const void* src) {
    asm volatile("cp.async.cg.shared.global [%0], [%1], 16;"
                 :: "r"(dst), "l"(src) : "memory");
}
__device__ __forceinline__ void cpa_commit() {
    asm volatile("cp.async.commit_group;" ::: "memory");
}
__device__ __forceinline__ void cpa_wait1() {
    asm volatile("cp.async.wait_group 1;" ::: "memory");
}
__device__ __forceinline__ void cpa_wait0() {
    asm volatile("cp.async.wait_group 0;" ::: "memory");
}

#define MMA_F16(ACC, A0, A1, A2, A3, B0, B1)                                  \
    asm volatile(                                                             \
        "mma.sync.aligned.m16n8k16.row.col.f32.f16.f16.f32 "                 \
        "{%0,%1,%2,%3}, {%4,%5,%6,%7}, {%8,%9}, {%0,%1,%2,%3};"              \
        : "+f"(ACC[0]), "+f"(ACC[1]), "+f"(ACC[2]), "+f"(ACC[3])             \
        : "r"(A0), "r"(A1), "r"(A2), "r"(A3), "r"(B0), "r"(B1))

// ---------------------------------------------------------------------------
// fp16x3 NT GEMM with cp.async pipeline.
// C[M,N] = alpha * (A hi/lo)[M,K] * ((B hi/lo)[N,K])^T + bias
// mode 0: write fp32 C.  mode 1: write split half oH/oL.
// M%256==0, N%128==0, K%32==0. Batched via blockIdx.z.
// ---------------------------------------------------------------------------
__global__ __launch_bounds__(NTH, 1)
void gemm_f16x3(const __half* __restrict__ aHg, const __half* __restrict__ aLg,
                const __half* __restrict__ bHg, const __half* __restrict__ bLg,
                const float* __restrict__ bias, float* __restrict__ C,
                __half* __restrict__ oH, __half* __restrict__ oL,
                int M, int N, int K, float alpha, int mode,
                long sA, long sB, long sC)
{
    extern __shared__ __align__(16) char dyn[];

    const long zb = blockIdx.z;
    aHg += zb * sA; aLg += zb * sA;
    bHg += zb * sB; bLg += zb * sB;
    if (C)  C  += zb * sC;
    if (oH) { oH += zb * sC; oL += zb * sC; }

    const int tid  = threadIdx.x;
    const int row0 = blockIdx.y * BM;
    const int col0 = blockIdx.x * BN;

    const int warp = tid >> 5;
    const int lane = tid & 31;
    const int wm   = warp >> 2;       // 0..3 (64-row slab)
    const int wn   = warp & 3;        // 0..3 (32-col slab)
    const int g    = lane >> 2;       // 0..7
    const int t4   = lane & 3;        // 0..3

    const unsigned sb = (unsigned)__cvta_generic_to_shared(dyn);

    // cp.async chunk mapping (per thread, per stage): 6 chunks of 16B.
    //  i=0,1: aH rows; i=2,3: aL rows; i=4: bH; i=5: bL
    const int arow0 = tid >> 2;              // 0..127
    const int apart = (tid & 3) * 8;         // half offset within row: 0,8,16,24
    // second A chunk: rows 128..255
    // B chunk: rows 0..127
    const __half* srcAH0 = aHg + (long)(row0 + arow0) * K + apart;
    const __half* srcAH1 = aHg + (long)(row0 + 128 + arow0) * K + apart;
    const __half* srcAL0 = aLg + (long)(row0 + arow0) * K + apart;
    const __half* srcAL1 = aLg + (long)(row0 + 128 + arow0) * K + apart;
    const __half* srcBH  = bHg + (long)(col0 + arow0) * K + apart;
    const __half* srcBL  = bLg + (long)(col0 + arow0) * K + apart;
    const unsigned dA0 = arow0 * (SROW * 2) + apart * 2;          // byte offsets
    const unsigned dA1 = (128 + arow0) * (SROW * 2) + apart * 2;
    const unsigned dB  = arow0 * (SROW * 2) + apart * 2;

    const int NIT = K / BK;

#define ISSUE(STG, IT)                                                        \
    {                                                                         \
        const long ko = (long)(IT) * BK;                                      \
        const unsigned st = sb + (STG) * STAGE_BYTES;                         \
        cpa16(st + O_AH + dA0, srcAH0 + ko);                                  \
        cpa16(st + O_AH + dA1, srcAH1 + ko);                                  \
        cpa16(st + O_AL + dA0, srcAL0 + ko);                                  \
        cpa16(st + O_AL + dA1, srcAL1 + ko);                                  \
        cpa16(st + O_BH + dB,  srcBH  + ko);                                  \
        cpa16(st + O_BL + dB,  srcBL  + ko);                                  \
        cpa_commit();                                                         \
    }

    float acc[4][4][4] = {};

    ISSUE(0, 0);
    ISSUE(1, 1);

    int cur = 0;
    for (int it = 0; it < NIT; it++) {
        if (it + 1 < NIT) cpa_wait1(); else cpa_wait0();
        __syncthreads();

        const __half* aH = (const __half*)(dyn + cur * STAGE_BYTES + O_AH);
        const __half* aL = (const __half*)(dyn + cur * STAGE_BYTES + O_AL);
        const __half* bH = (const __half*)(dyn + cur * STAGE_BYTES + O_BH);
        const __half* bL = (const __half*)(dyn + cur * STAGE_BYTES + O_BL);

        #pragma unroll
        for (int ks = 0; ks < 2; ks++) {
            const int kk = ks * 16;

            unsigned afH[4][4], afL[4][4];
            #pragma unroll
            for (int mt = 0; mt < 4; mt++) {
                const int m = wm * 64 + mt * 16 + g;
                const int i0 = m * SROW + kk + 2 * t4;
                const int i1 = (m + 8) * SROW + kk + 2 * t4;
                afH[mt][0] = *(const unsigned*)&aH[i0];
                afH[mt][1] = *(const unsigned*)&aH[i1];
                afH[mt][2] = *(const unsigned*)&aH[i0 + 8];
                afH[mt][3] = *(const unsigned*)&aH[i1 + 8];
                afL[mt][0] = *(const unsigned*)&aL[i0];
                afL[mt][1] = *(const unsigned*)&aL[i1];
                afL[mt][2] = *(const unsigned*)&aL[i0 + 8];
                afL[mt][3] = *(const unsigned*)&aL[i1 + 8];
            }
            unsigned bfH[4][2], bfL[4][2];
            #pragma unroll
            for (int nt = 0; nt < 4; nt++) {
                const int n = wn * 32 + nt * 8 + g;
                const int j0 = n * SROW + kk + 2 * t4;
                bfH[nt][0] = *(const unsigned*)&bH[j0];
                bfH[nt][1] = *(const unsigned*)&bH[j0 + 8];
                bfL[nt][0] = *(const unsigned*)&bL[j0];
                bfL[nt][1] = *(const unsigned*)&bL[j0 + 8];
            }
            #pragma unroll
            for (int mt = 0; mt < 4; mt++)
                #pragma unroll
                for (int nt = 0; nt < 4; nt++) {
                    float* a4 = acc[mt][nt];
                    MMA_F16(a4, afL[mt][0], afL[mt][1], afL[mt][2], afL[mt][3],
                            bfH[nt][0], bfH[nt][1]);
                    MMA_F16(a4, afH[mt][0], afH[mt][1], afH[mt][2], afH[mt][3],
                            bfL[nt][0], bfL[nt][1]);
                    MMA_F16(a4, afH[mt][0], afH[mt][1], afH[mt][2], afH[mt][3],
                            bfH[nt][0], bfH[nt][1]);
                }
        }

        if (it + 2 < NIT) ISSUE((cur + 2) % NSTAGES, it + 2);
        if (++cur == NSTAGES) cur = 0;
    }
#undef ISSUE

    // ---- epilogue ----
    #pragma unroll
    for (int mt = 0; mt < 4; mt++) {
        const int r = row0 + wm * 64 + mt * 16 + g;
        #pragma unroll
        for (int nt = 0; nt < 4; nt++) {
            const int c = col0 + wn * 32 + nt * 8 + 2 * t4;
            float b0 = 0.f, b1 = 0.f;
            if (bias) { b0 = bias[c]; b1 = bias[c + 1]; }
            float2 v0, v1;
            v0.x = alpha * acc[mt][nt][0] + b0;
            v0.y = alpha * acc[mt][nt][1] + b1;
            v1.x = alpha * acc[mt][nt][2] + b0;
            v1.y = alpha * acc[mt][nt][3] + b1;
            if (mode == 0) {
                *(float2*)(C + (long)r * N + c)       = v0;
                *(float2*)(C + (long)(r + 8) * N + c) = v1;
            } else {
                unsigned h, l;
                split2(v0.x, v0.y, h, l);
                *(unsigned*)(oH + (long)r * N + c) = h;
                *(unsigned*)(oL + (long)r * N + c) = l;
                split2(v1.x, v1.y, h, l);
                *(unsigned*)(oH + (long)(r + 8) * N + c) = h;
                *(unsigned*)(oL + (long)(r + 8) * N + c) = l;
            }
        }
    }
}

// ---------------------------------------------------------------------------
// Elementwise split: fp32 -> half hi/lo
// ---------------------------------------------------------------------------
__global__ __launch_bounds__(256)
void split_hl(const float* __restrict__ in, __half* __restrict__ oH,
              __half* __restrict__ oL, long n4)
{
    const long i = (long)blockIdx.x * 256 + threadIdx.x;
    if (i >= n4) return;
    float4 v = *(const float4*)(in + 4 * i);
    uint2 hh, ll;
    split2(v.x, v.y, hh.x, ll.x);
    split2(v.z, v.w, hh.y, ll.y);
    *(uint2*)(oH + 4 * i) = hh;
    *(uint2*)(oL + 4 * i) = ll;
}

// ---------------------------------------------------------------------------
// Transpose + split: in[R,C] fp32 -> oH/oL[C,R] half. Batched via z.
// ---------------------------------------------------------------------------
__global__ __launch_bounds__(256)
void transpose_split(const float* __restrict__ in,
                     __half* __restrict__ oH, __half* __restrict__ oL,
                     int R, int C, long sIn, long sOut)
{
    __shared__ float t[32][33];
    in += (long)blockIdx.z * sIn;
    oH += (long)blockIdx.z * sOut;
    oL += (long)blockIdx.z * sOut;
    const int tx = threadIdx.x & 31;
    const int ty = threadIdx.x >> 5;
    const int bx = blockIdx.x * 32;
    const int by = blockIdx.y * 32;
    #pragma unroll
    for (int jj = 0; jj < 4; jj++)
        t[ty + 8 * jj][tx] = in[(long)(by + ty + 8 * jj) * C + bx + tx];
    __syncthreads();
    #pragma unroll
    for (int jj = 0; jj < 4; jj++) {
        const float f = t[tx][ty + 8 * jj];
        const __half h = __float2half_rn(f);
        const __half l = __float2half_rn(f - __half2float(h));
        const long o = (long)(bx + ty + 8 * jj) * R + by + tx;
        oH[o] = h;
        oL[o] = l;
    }
}

// ---------------------------------------------------------------------------
// Row softmax over 2048 cols + split to half hi/lo. One block per row.
// ---------------------------------------------------------------------------
__global__ __launch_bounds__(256)
void softmax_split(const float* __restrict__ sim,
                   __half* __restrict__ oH, __half* __restrict__ oL)
{
    const float* p = sim + (long)blockIdx.x * SEQ;
    __half* ph = oH + (long)blockIdx.x * SEQ;
    __half* pl = oL + (long)blockIdx.x * SEQ;
    const int tid = threadIdx.x;

    float v[8];
    float mx = -1e30f;
    #pragma unroll
    for (int i = 0; i < 8; i++) {
        v[i] = p[tid + i * 256];
        mx = fmaxf(mx, v[i]);
    }
    #pragma unroll
    for (int o = 16; o; o >>= 1)
        mx = fmaxf(mx, __shfl_xor_sync(0xffffffffu, mx, o));
    __shared__ float red[8];
    if ((tid & 31) == 0) red[tid >> 5] = mx;
    __syncthreads();
    mx = red[0];
    #pragma unroll
    for (int w = 1; w < 8; w++) mx = fmaxf(mx, red[w]);

    float s = 0.f;
    #pragma unroll
    for (int i = 0; i < 8; i++) {
        v[i] = __expf(v[i] - mx);
        s += v[i];
    }
    #pragma unroll
    for (int o = 16; o; o >>= 1)
        s += __shfl_xor_sync(0xffffffffu, s, o);
    __syncthreads();
    if ((tid & 31) == 0) red[tid >> 5] = s;
    __syncthreads();
    s = red[0];
    #pragma unroll
    for (int w = 1; w < 8; w++) s += red[w];

    const float inv = 1.0f / s;
    #pragma unroll
    for (int i = 0; i < 8; i++) {
        const float a = v[i] * inv;
        const __half h = __float2half_rn(a);
        const __half l = __float2half_rn(a - __half2float(h));
        ph[tid + i * 256] = h;
        pl[tid + i * 256] = l;
    }
}

// ---------------------------------------------------------------------------
// Launch
// ---------------------------------------------------------------------------
extern "C" void kernel_launch(void* const* d_in, const int* in_sizes, int n_in,
                              void* d_out, int out_size)
{
    const float* x  = (const float*)d_in[0];
    const float* Wq = (const float*)d_in[1];
    const float* bq = (const float*)d_in[2];
    const float* Wk = (const float*)d_in[3];
    const float* bk = (const float*)d_in[4];
    const float* Wv = (const float*)d_in[5];
    const float* bv = (const float*)d_in[6];
    float* out = (float*)d_out;

    __half *xH, *xL, *wH, *wL, *qH, *qL, *kH, *kL, *vtH, *vtL, *aH, *aL;
    float *v, *sim;
    cudaGetSymbolAddress((void**)&xH, g_xH);
    cudaGetSymbolAddress((void**)&xL, g_xL);
    cudaGetSymbolAddress((void**)&wH, g_wH);
    cudaGetSymbolAddress((void**)&wL, g_wL);
    cudaGetSymbolAddress((void**)&qH, g_qH);
    cudaGetSymbolAddress((void**)&qL, g_qL);
    cudaGetSymbolAddress((void**)&kH, g_kH);
    cudaGetSymbolAddress((void**)&kL, g_kL);
    cudaGetSymbolAddress((void**)&v,   g_v);
    cudaGetSymbolAddress((void**)&vtH, g_vtH);
    cudaGetSymbolAddress((void**)&vtL, g_vtL);
    cudaGetSymbolAddress((void**)&sim, g_sim);
    cudaGetSymbolAddress((void**)&aH, g_aH);
    cudaGetSymbolAddress((void**)&aL, g_aL);

    cudaFuncSetAttribute(gemm_f16x3,
                         cudaFuncAttributeMaxDynamicSharedMemorySize,
                         SMEM_BYTES);

    __half* wqH = wH;
    __half* wqL = wL;
    __half* wkH = wH + (size_t)DIM * DIM;
    __half* wkL = wL + (size_t)DIM * DIM;
    __half* wvH = wH + 2 * (size_t)DIM * DIM;
    __half* wvL = wL + 2 * (size_t)DIM * DIM;

    // 0a) split x into half hi/lo
    {
        const long n4 = (long)MROWS * DIM / 4;
        split_hl<<<(unsigned)((n4 + 255) / 256), 256>>>(x, xH, xL, n4);
    }
    // 0b) transpose+split weights: W[k][n] -> wH/wL[n][k]
    {
        dim3 grid(DIM / 32, DIM / 32, 1);
        transpose_split<<<grid, 256>>>(Wq, wqH, wqL, DIM, DIM, 0, 0);
        transpose_split<<<grid, 256>>>(Wk, wkH, wkL, DIM, DIM, 0, 0);
        transpose_split<<<grid, 256>>>(Wv, wvH, wvL, DIM, DIM, 0, 0);
    }

    // 1) QKV projections: Q,K written split; V written fp32
    {
        dim3 grid(DIM / BN, MROWS / BM, 1);
        gemm_f16x3<<<grid, NTH, SMEM_BYTES>>>(xH, xL, wqH, wqL, bq,
                                              nullptr, qH, qL,
                                              MROWS, DIM, DIM, 1.0f, 1, 0, 0, 0);
        gemm_f16x3<<<grid, NTH, SMEM_BYTES>>>(xH, xL, wkH, wkL, bk,
                                              nullptr, kH, kL,
                                              MROWS, DIM, DIM, 1.0f, 1, 0, 0, 0);
        gemm_f16x3<<<grid, NTH, SMEM_BYTES>>>(xH, xL, wvH, wvL, bv,
                                              v, nullptr, nullptr,
                                              MROWS, DIM, DIM, 1.0f, 0, 0, 0, 0);
    }

    // 1b) transpose+split V per batch: v[b][s][d] -> vtH/vtL[b][d][s]
    {
        dim3 grid(DIM / 32, SEQ / 32, BATCH);
        transpose_split<<<grid, 256>>>(v, vtH, vtL, SEQ, DIM,
                                       (long)SEQ * DIM, (long)SEQ * DIM);
    }

    // 2) sim[b] = Q[b] @ K[b]^T * SCALE -> fp32
    {
        dim3 grid(SEQ / BN, SEQ / BM, BATCH);
        gemm_f16x3<<<grid, NTH, SMEM_BYTES>>>(qH, qL, kH, kL, nullptr,
                                              sim, nullptr, nullptr,
                                              SEQ, SEQ, DIM, SCALE, 0,
                                              (long)SEQ * DIM, (long)SEQ * DIM,
                                              (long)SEQ * SEQ);
    }

    // 3) softmax + split
    softmax_split<<<MROWS, 256>>>(sim, aH, aL);

    // 4) out[b] = attn[b] @ Vt[b]^T -> fp32
    {
        dim3 grid(DIM / BN, SEQ / BM, BATCH);
        gemm_f16x3<<<grid, NTH, SMEM_BYTES>>>(aH, aL, vtH, vtL, nullptr,
                                              out, nullptr, nullptr,
                                              SEQ, DIM, SEQ, 1.0f, 0,
                                              (long)SEQ * SEQ, (long)DIM * SEQ,
                                              (long)SEQ * DIM);
    }
}

// round 12
// speedup vs baseline: 2.8041x; 1.0501x over previous
#include <cuda_runtime.h>
#include <cuda_fp16.h>
#include <cstdint>
#include <math.h>

// Problem constants
#define BATCH 16
#define SEQ   2048
#define DIM   512
#define MROWS (BATCH * SEQ)   // 32768
#define SCALE 0.125f

// GEMM tile config: CTA 256x128, BK=32, 512 threads (16 warps, 4x4), warp 64x32
#define BM 256
#define BN 128
#define BK 32
#define NTH 512

#define SROW 40                      // halves per row (32 + 8 pad)
#define O_AH 0
#define O_AL (BM * SROW * 2)         // 20480
#define O_BH (2 * BM * SROW * 2)     // 40960
#define O_BL (O_BH + BN * SROW * 2)  // 51200
#define STAGE_BYTES (O_BL + BN * SROW * 2)   // 61440
#define NSTAGES 3
#define SMEM_BYTES (NSTAGES * STAGE_BYTES)   // 184320

// ---------------------------------------------------------------------------
// Scratch (device globals — no allocation allowed)
// ---------------------------------------------------------------------------
__device__ __half g_xH[(size_t)MROWS * DIM];
__device__ __half g_xL[(size_t)MROWS * DIM];
__device__ __half g_wH[3 * (size_t)DIM * DIM];
__device__ __half g_wL[3 * (size_t)DIM * DIM];
__device__ __half g_qH[(size_t)MROWS * DIM];
__device__ __half g_qL[(size_t)MROWS * DIM];
__device__ __half g_kH[(size_t)MROWS * DIM];
__device__ __half g_kL[(size_t)MROWS * DIM];
__device__ float  g_v [(size_t)MROWS * DIM];
__device__ __half g_vtH[(size_t)MROWS * DIM];
__device__ __half g_vtL[(size_t)MROWS * DIM];
__device__ float  g_sim[(size_t)BATCH * SEQ * SEQ];
__device__ float2 g_stats[(size_t)MROWS];

// ---------------------------------------------------------------------------
// Helpers
// ---------------------------------------------------------------------------
__device__ __forceinline__ void split2(float a, float b, unsigned &h, unsigned &l) {
    __half2 hh = __floats2half2_rn(a, b);
    float2 r = __half22float2(hh);
    __half2 ll = __floats2half2_rn(a - r.x, b - r.y);
    h = *(unsigned*)&hh;
    l = *(unsigned*)&ll;
}

__device__ __forceinline__ void cpa16(unsigned dst, const void* src) {
    asm volatile("cp.async.cg.shared.global [%0], [%1], 16;"
                 :: "r"(dst), "l"(src) : "memory");
}
__device__ __forceinline__ void cpa_commit() {
    asm volatile("cp.async.commit_group;" ::: "memory");
}
__device__ __forceinline__ void cpa_wait1() {
    asm volatile("cp.async.wait_group 1;" ::: "memory");
}
__device__ __forceinline__ void cpa_wait0() {
    asm volatile("cp.async.wait_group 0;" ::: "memory");
}

#define MMA_F16(ACC, A0, A1, A2, A3, B0, B1)                                  \
    asm volatile(                                                             \
        "mma.sync.aligned.m16n8k16.row.col.f32.f16.f16.f32 "                 \
        "{%0,%1,%2,%3}, {%4,%5,%6,%7}, {%8,%9}, {%0,%1,%2,%3};"              \
        : "+f"(ACC[0]), "+f"(ACC[1]), "+f"(ACC[2]), "+f"(ACC[3])             \
        : "r"(A0), "r"(A1), "r"(A2), "r"(A3), "r"(B0), "r"(B1))

#define LDM_X4(R0, R1, R2, R3, ADDR)                                          \
    asm volatile("ldmatrix.sync.aligned.m8n8.x4.shared.b16 {%0,%1,%2,%3}, [%4];" \
        : "=r"(R0), "=r"(R1), "=r"(R2), "=r"(R3) : "r"(ADDR))

// ---------------------------------------------------------------------------
// Shared compute tile: 2 k-steps of fp16x3 MMAs using ldmatrix fragments.
// ---------------------------------------------------------------------------
__device__ __forceinline__ void compute_tile(unsigned stb, unsigned aoff,
                                             unsigned boff, float acc[4][4][4])
{
    #pragma unroll
    for (int ks = 0; ks < 2; ks++) {
        const unsigned kb = ks * 32;   // 16 halves = 32 bytes

        unsigned afH[4][4], afL[4][4];
        #pragma unroll
        for (int mt = 0; mt < 4; mt++) {
            const unsigned ah = stb + O_AH + aoff + mt * (16 * SROW * 2) + kb;
            const unsigned al = stb + O_AL + aoff + mt * (16 * SROW * 2) + kb;
            LDM_X4(afH[mt][0], afH[mt][1], afH[mt][2], afH[mt][3], ah);
            LDM_X4(afL[mt][0], afL[mt][1], afL[mt][2], afL[mt][3], al);
        }
        unsigned bfH[4][2], bfL[4][2];
        #pragma unroll
        for (int p = 0; p < 2; p++) {
            const unsigned bh = stb + O_BH + boff + p * (16 * SROW * 2) + kb;
            const unsigned bl = stb + O_BL + boff + p * (16 * SROW * 2) + kb;
            LDM_X4(bfH[2*p][0], bfH[2*p][1], bfH[2*p+1][0], bfH[2*p+1][1], bh);
            LDM_X4(bfL[2*p][0], bfL[2*p][1], bfL[2*p+1][0], bfL[2*p+1][1], bl);
        }
        #pragma unroll
        for (int mt = 0; mt < 4; mt++)
            #pragma unroll
            for (int nt = 0; nt < 4; nt++) {
                float* a4 = acc[mt][nt];
                MMA_F16(a4, afL[mt][0], afL[mt][1], afL[mt][2], afL[mt][3],
                        bfH[nt][0], bfH[nt][1]);
                MMA_F16(a4, afH[mt][0], afH[mt][1], afH[mt][2], afH[mt][3],
                        bfL[nt][0], bfL[nt][1]);
                MMA_F16(a4, afH[mt][0], afH[mt][1], afH[mt][2], afH[mt][3],
                        bfH[nt][0], bfH[nt][1]);
            }
    }
}

// Per-thread ldmatrix offsets. A: tiles (t8&1 -> +8 rows, t8>>1 -> +8 k).
// B: tiles (t8>>1 -> +8 rows, t8&1 -> +8 k).
__device__ __forceinline__ void frag_offsets(int warp, int lane,
                                             unsigned &aoff, unsigned &boff)
{
    const int wm = warp >> 2, wn = warp & 3;
    const int t8 = lane >> 3, r8 = lane & 7;
    aoff = ((wm * 64 + ((t8 & 1) << 3) + r8) * SROW + ((t8 >> 1) << 3)) * 2;
    boff = ((wn * 32 + ((t8 >> 1) << 3) + r8) * SROW + ((t8 & 1) << 3)) * 2;
}

// ---------------------------------------------------------------------------
// fp16x3 NT GEMM with cp.async pipeline (QKV projections + sim).
// ---------------------------------------------------------------------------
__global__ __launch_bounds__(NTH, 1)
void gemm_f16x3(const __half* __restrict__ aHg, const __half* __restrict__ aLg,
                const __half* __restrict__ bHg, const __half* __restrict__ bLg,
                const float* __restrict__ bias, float* __restrict__ C,
                __half* __restrict__ oH, __half* __restrict__ oL,
                int M, int N, int K, float alpha, int mode,
                long sA, long sB, long sC)
{
    extern __shared__ __align__(16) char dyn[];

    const long zb = blockIdx.z;
    aHg += zb * sA; aLg += zb * sA;
    bHg += zb * sB; bLg += zb * sB;
    if (C)  C  += zb * sC;
    if (oH) { oH += zb * sC; oL += zb * sC; }

    const int tid  = threadIdx.x;
    const int row0 = blockIdx.y * BM;
    const int col0 = blockIdx.x * BN;

    const int warp = tid >> 5;
    const int lane = tid & 31;
    const int wm   = warp >> 2;
    const int wn   = warp & 3;
    const int g    = lane >> 2;
    const int t4   = lane & 3;

    const unsigned sb = (unsigned)__cvta_generic_to_shared(dyn);
    unsigned aoff, boff;
    frag_offsets(warp, lane, aoff, boff);

    const int arow0 = tid >> 2;
    const int apart = (tid & 3) * 8;
    const __half* srcAH0 = aHg + (long)(row0 + arow0) * K + apart;
    const __half* srcAH1 = aHg + (long)(row0 + 128 + arow0) * K + apart;
    const __half* srcAL0 = aLg + (long)(row0 + arow0) * K + apart;
    const __half* srcAL1 = aLg + (long)(row0 + 128 + arow0) * K + apart;
    const __half* srcBH  = bHg + (long)(col0 + arow0) * K + apart;
    const __half* srcBL  = bLg + (long)(col0 + arow0) * K + apart;
    const unsigned dA0 = arow0 * (SROW * 2) + apart * 2;
    const unsigned dA1 = (128 + arow0) * (SROW * 2) + apart * 2;
    const unsigned dB  = arow0 * (SROW * 2) + apart * 2;

    const int NIT = K / BK;

#define ISSUE(STG, IT)                                                        \
    {                                                                         \
        const long ko = (long)(IT) * BK;                                      \
        const unsigned st = sb + (STG) * STAGE_BYTES;                         \
        cpa16(st + O_AH + dA0, srcAH0 + ko);                                  \
        cpa16(st + O_AH + dA1, srcAH1 + ko);                                  \
        cpa16(st + O_AL + dA0, srcAL0 + ko);                                  \
        cpa16(st + O_AL + dA1, srcAL1 + ko);                                  \
        cpa16(st + O_BH + dB,  srcBH  + ko);                                  \
        cpa16(st + O_BL + dB,  srcBL  + ko);                                  \
        cpa_commit();                                                         \
    }

    float acc[4][4][4] = {};

    ISSUE(0, 0);
    ISSUE(1, 1);

    int cur = 0;
    for (int it = 0; it < NIT; it++) {
        if (it + 1 < NIT) cpa_wait1(); else cpa_wait0();
        __syncthreads();

        compute_tile(sb + cur * STAGE_BYTES, aoff, boff, acc);

        if (it + 2 < NIT) ISSUE((cur + 2) % NSTAGES, it + 2);
        if (++cur == NSTAGES) cur = 0;
    }
#undef ISSUE

    // ---- epilogue ----
    #pragma unroll
    for (int mt = 0; mt < 4; mt++) {
        const int r = row0 + wm * 64 + mt * 16 + g;
        #pragma unroll
        for (int nt = 0; nt < 4; nt++) {
            const int c = col0 + wn * 32 + nt * 8 + 2 * t4;
            float b0 = 0.f, b1 = 0.f;
            if (bias) { b0 = bias[c]; b1 = bias[c + 1]; }
            float2 v0, v1;
            v0.x = alpha * acc[mt][nt][0] + b0;
            v0.y = alpha * acc[mt][nt][1] + b1;
            v1.x = alpha * acc[mt][nt][2] + b0;
            v1.y = alpha * acc[mt][nt][3] + b1;
            if (mode == 0) {
                *(float2*)(C + (long)r * N + c)       = v0;
                *(float2*)(C + (long)(r + 8) * N + c) = v1;
            } else {
                unsigned h, l;
                split2(v0.x, v0.y, h, l);
                *(unsigned*)(oH + (long)r * N + c) = h;
                *(unsigned*)(oL + (long)r * N + c) = l;
                split2(v1.x, v1.y, h, l);
                *(unsigned*)(oH + (long)(r + 8) * N + c) = h;
                *(unsigned*)(oL + (long)(r + 8) * N + c) = l;
            }
        }
    }
}

// ---------------------------------------------------------------------------
// Fused attn@V GEMM: A = softmax(sim) computed on the fly from raw sim + row
// stats; B = Vt (split halves, cp.async). out fp32.
// ---------------------------------------------------------------------------
__global__ __launch_bounds__(NTH, 1)
void gemm_av(const float* __restrict__ sim, const float2* __restrict__ stats,
             const __half* __restrict__ bHg, const __half* __restrict__ bLg,
             float* __restrict__ C, int N, int K,
             long sA, long sB, long sC)
{
    extern __shared__ __align__(16) char dyn[];

    const long zb = blockIdx.z;
    sim += zb * sA;
    bHg += zb * sB; bLg += zb * sB;
    C   += zb * sC;

    const int tid  = threadIdx.x;
    const int row0 = blockIdx.y * BM;
    const int col0 = blockIdx.x * BN;

    const int warp = tid >> 5;
    const int lane = tid & 31;
    const int wm   = warp >> 2;
    const int wn   = warp & 3;
    const int g    = lane >> 2;
    const int t4   = lane & 3;

    const unsigned sb = (unsigned)__cvta_generic_to_shared(dyn);
    unsigned aoff, boff;
    frag_offsets(warp, lane, aoff, boff);

    // A loader: 2 threads/row, 16 fp32 each, fused exp
    const int arow = tid >> 1;               // 0..255
    const int ak0  = (tid & 1) * 16;
    const float* srcA = sim + (long)(row0 + arow) * K + ak0;
    const float2 st = stats[zb * SEQ + row0 + arow];
    const float mx = st.x, inv = st.y;
    const unsigned dA = arow * (SROW * 2) + ak0 * 2;

    // B loader: cp.async, 1 thread per (row, quarter)
    const int brow = tid >> 2;
    const int bpart = (tid & 3) * 8;
    const __half* srcBH = bHg + (long)(col0 + brow) * K + bpart;
    const __half* srcBL = bLg + (long)(col0 + brow) * K + bpart;
    const unsigned dB = brow * (SROW * 2) + bpart * 2;

    const int NIT = K / BK;
    float4 aReg[4];

#define LOADA(IT)                                                             \
    {                                                                         \
        const long ko = (long)(IT) * BK;                                      \
        _Pragma("unroll")                                                     \
        for (int i = 0; i < 4; i++)                                           \
            aReg[i] = *(const float4*)(srcA + ko + 4 * i);                    \
    }
#define STSA(STG)                                                             \
    {                                                                         \
        char* st_ = dyn + (STG) * STAGE_BYTES;                                \
        _Pragma("unroll")                                                     \
        for (int i = 0; i < 4; i++) {                                         \
            float p0 = __expf(aReg[i].x - mx) * inv;                          \
            float p1 = __expf(aReg[i].y - mx) * inv;                          \
            float p2 = __expf(aReg[i].z - mx) * inv;                          \
            float p3 = __expf(aReg[i].w - mx) * inv;                          \
            uint2 hh, ll;                                                     \
            split2(p0, p1, hh.x, ll.x);                                       \
            split2(p2, p3, hh.y, ll.y);                                       \
            *(uint2*)(st_ + O_AH + dA + 8 * i) = hh;                          \
            *(uint2*)(st_ + O_AL + dA + 8 * i) = ll;                          \
        }                                                                     \
    }
#define ISSUEB(STG, IT)                                                       \
    {                                                                         \
        const long ko = (long)(IT) * BK;                                      \
        const unsigned st = sb + (STG) * STAGE_BYTES;                         \
        cpa16(st + O_BH + dB, srcBH + ko);                                    \
        cpa16(st + O_BL + dB, srcBL + ko);                                    \
        cpa_commit();                                                         \
    }

    float acc[4][4][4] = {};

    LOADA(0); STSA(0);
    LOADA(1); STSA(1);
    ISSUEB(0, 0);
    ISSUEB(1, 1);

    int cur = 0;
    for (int it = 0; it < NIT; it++) {
        if (it + 1 < NIT) cpa_wait1(); else cpa_wait0();
        __syncthreads();

        if (it + 2 < NIT) LOADA(it + 2);

        compute_tile(sb + cur * STAGE_BYTES, aoff, boff, acc);

        if (it + 2 < NIT) {
            STSA((cur + 2) % NSTAGES);
            ISSUEB((cur + 2) % NSTAGES, it + 2);
        }
        if (++cur == NSTAGES) cur = 0;
    }
#undef LOADA
#undef STSA
#undef ISSUEB

    // ---- epilogue: fp32 out ----
    #pragma unroll
    for (int mt = 0; mt < 4; mt++) {
        const int r = row0 + wm * 64 + mt * 16 + g;
        #pragma unroll
        for (int nt = 0; nt < 4; nt++) {
            const int c = col0 + wn * 32 + nt * 8 + 2 * t4;
            float2 v0, v1;
            v0.x = acc[mt][nt][0];
            v0.y = acc[mt][nt][1];
            v1.x = acc[mt][nt][2];
            v1.y = acc[mt][nt][3];
            *(float2*)(C + (long)r * N + c)       = v0;
            *(float2*)(C + (long)(r + 8) * N + c) = v1;
        }
    }
}

// ---------------------------------------------------------------------------
// Row stats: max + 1/sum(exp) over SEQ=2048 cols. One block per row.
// ---------------------------------------------------------------------------
__global__ __launch_bounds__(256)
void rowstat(const float* __restrict__ sim, float2* __restrict__ stats)
{
    const float* p = sim + (long)blockIdx.x * SEQ;
    const int tid = threadIdx.x;

    float v[8];
    float mx = -1e30f;
    #pragma unroll
    for (int i = 0; i < 8; i++) {
        v[i] = p[tid + i * 256];
        mx = fmaxf(mx, v[i]);
    }
    #pragma unroll
    for (int o = 16; o; o >>= 1)
        mx = fmaxf(mx, __shfl_xor_sync(0xffffffffu, mx, o));
    __shared__ float red[8];
    if ((tid & 31) == 0) red[tid >> 5] = mx;
    __syncthreads();
    mx = red[0];
    #pragma unroll
    for (int w = 1; w < 8; w++) mx = fmaxf(mx, red[w]);

    float s = 0.f;
    #pragma unroll
    for (int i = 0; i < 8; i++)
        s += __expf(v[i] - mx);
    #pragma unroll
    for (int o = 16; o; o >>= 1)
        s += __shfl_xor_sync(0xffffffffu, s, o);
    __syncthreads();
    if ((tid & 31) == 0) red[tid >> 5] = s;
    __syncthreads();
    s = red[0];
    #pragma unroll
    for (int w = 1; w < 8; w++) s += red[w];

    if (tid == 0) {
        float2 st;
        st.x = mx;
        st.y = 1.0f / s;
        stats[blockIdx.x] = st;
    }
}

// ---------------------------------------------------------------------------
// Elementwise split: fp32 -> half hi/lo
// ---------------------------------------------------------------------------
__global__ __launch_bounds__(256)
void split_hl(const float* __restrict__ in, __half* __restrict__ oH,
              __half* __restrict__ oL, long n4)
{
    const long i = (long)blockIdx.x * 256 + threadIdx.x;
    if (i >= n4) return;
    float4 v = *(const float4*)(in + 4 * i);
    uint2 hh, ll;
    split2(v.x, v.y, hh.x, ll.x);
    split2(v.z, v.w, hh.y, ll.y);
    *(uint2*)(oH + 4 * i) = hh;
    *(uint2*)(oL + 4 * i) = ll;
}

// ---------------------------------------------------------------------------
// Transpose + split: in[R,C] fp32 -> oH/oL[C,R] half. Batched via z.
// ---------------------------------------------------------------------------
__global__ __launch_bounds__(256)
void transpose_split(const float* __restrict__ in,
                     __half* __restrict__ oH, __half* __restrict__ oL,
                     int R, int C, long sIn, long sOut)
{
    __shared__ float t[32][33];
    in += (long)blockIdx.z * sIn;
    oH += (long)blockIdx.z * sOut;
    oL += (long)blockIdx.z * sOut;
    const int tx = threadIdx.x & 31;
    const int ty = threadIdx.x >> 5;
    const int bx = blockIdx.x * 32;
    const int by = blockIdx.y * 32;
    #pragma unroll
    for (int jj = 0; jj < 4; jj++)
        t[ty + 8 * jj][tx] = in[(long)(by + ty + 8 * jj) * C + bx + tx];
    __syncthreads();
    #pragma unroll
    for (int jj = 0; jj < 4; jj++) {
        const float f = t[tx][ty + 8 * jj];
        const __half h = __float2half_rn(f);
        const __half l = __float2half_rn(f - __half2float(h));
        const long o = (long)(bx + ty + 8 * jj) * R + by + tx;
        oH[o] = h;
        oL[o] = l;
    }
}

// ---------------------------------------------------------------------------
// Launch
// ---------------------------------------------------------------------------
extern "C" void kernel_launch(void* const* d_in, const int* in_sizes, int n_in,
                              void* d_out, int out_size)
{
    const float* x  = (const float*)d_in[0];
    const float* Wq = (const float*)d_in[1];
    const float* bq = (const float*)d_in[2];
    const float* Wk = (const float*)d_in[3];
    const float* bk = (const float*)d_in[4];
    const float* Wv = (const float*)d_in[5];
    const float* bv = (const float*)d_in[6];
    float* out = (float*)d_out;

    __half *xH, *xL, *wH, *wL, *qH, *qL, *kH, *kL, *vtH, *vtL;
    float *v, *sim;
    float2* stats;
    cudaGetSymbolAddress((void**)&xH, g_xH);
    cudaGetSymbolAddress((void**)&xL, g_xL);
    cudaGetSymbolAddress((void**)&wH, g_wH);
    cudaGetSymbolAddress((void**)&wL, g_wL);
    cudaGetSymbolAddress((void**)&qH, g_qH);
    cudaGetSymbolAddress((void**)&qL, g_qL);
    cudaGetSymbolAddress((void**)&kH, g_kH);
    cudaGetSymbolAddress((void**)&kL, g_kL);
    cudaGetSymbolAddress((void**)&v,   g_v);
    cudaGetSymbolAddress((void**)&vtH, g_vtH);
    cudaGetSymbolAddress((void**)&vtL, g_vtL);
    cudaGetSymbolAddress((void**)&sim, g_sim);
    cudaGetSymbolAddress((void**)&stats, g_stats);

    cudaFuncSetAttribute(gemm_f16x3,
                         cudaFuncAttributeMaxDynamicSharedMemorySize,
                         SMEM_BYTES);
    cudaFuncSetAttribute(gemm_av,
                         cudaFuncAttributeMaxDynamicSharedMemorySize,
                         SMEM_BYTES);

    __half* wqH = wH;
    __half* wqL = wL;
    __half* wkH = wH + (size_t)DIM * DIM;
    __half* wkL = wL + (size_t)DIM * DIM;
    __half* wvH = wH + 2 * (size_t)DIM * DIM;
    __half* wvL = wL + 2 * (size_t)DIM * DIM;

    // 0a) split x into half hi/lo
    {
        const long n4 = (long)MROWS * DIM / 4;
        split_hl<<<(unsigned)((n4 + 255) / 256), 256>>>(x, xH, xL, n4);
    }
    // 0b) transpose+split weights: W[k][n] -> wH/wL[n][k]
    {
        dim3 grid(DIM / 32, DIM / 32, 1);
        transpose_split<<<grid, 256>>>(Wq, wqH, wqL, DIM, DIM, 0, 0);
        transpose_split<<<grid, 256>>>(Wk, wkH, wkL, DIM, DIM, 0, 0);
        transpose_split<<<grid, 256>>>(Wv, wvH, wvL, DIM, DIM, 0, 0);
    }

    // 1) QKV projections: Q,K written split; V written fp32
    {
        dim3 grid(DIM / BN, MROWS / BM, 1);
        gemm_f16x3<<<grid, NTH, SMEM_BYTES>>>(xH, xL, wqH, wqL, bq,
                                              nullptr, qH, qL,
                                              MROWS, DIM, DIM, 1.0f, 1, 0, 0, 0);
        gemm_f16x3<<<grid, NTH, SMEM_BYTES>>>(xH, xL, wkH, wkL, bk,
                                              nullptr, kH, kL,
                                              MROWS, DIM, DIM, 1.0f, 1, 0, 0, 0);
        gemm_f16x3<<<grid, NTH, SMEM_BYTES>>>(xH, xL, wvH, wvL, bv,
                                              v, nullptr, nullptr,
                                              MROWS, DIM, DIM, 1.0f, 0, 0, 0, 0);
    }

    // 1b) transpose+split V per batch: v[b][s][d] -> vtH/vtL[b][d][s]
    {
        dim3 grid(DIM / 32, SEQ / 32, BATCH);
        transpose_split<<<grid, 256>>>(v, vtH, vtL, SEQ, DIM,
                                       (long)SEQ * DIM, (long)SEQ * DIM);
    }

    // 2) sim[b] = Q[b] @ K[b]^T * SCALE -> fp32
    {
        dim3 grid(SEQ / BN, SEQ / BM, BATCH);
        gemm_f16x3<<<grid, NTH, SMEM_BYTES>>>(qH, qL, kH, kL, nullptr,
                                              sim, nullptr, nullptr,
                                              SEQ, SEQ, DIM, SCALE, 0,
                                              (long)SEQ * DIM, (long)SEQ * DIM,
                                              (long)SEQ * SEQ);
    }

    // 3) row stats (max, 1/sum)
    rowstat<<<MROWS, 256>>>(sim, stats);

    // 4) out[b] = softmax(sim[b]) @ Vt[b]^T -> fp32 (softmax fused in loader)
    {
        dim3 grid(DIM / BN, SEQ / BM, BATCH);
        gemm_av<<<grid, NTH, SMEM_BYTES>>>(sim, stats, vtH, vtL, out,
                                           DIM, SEQ,
                                           (long)SEQ * SEQ, (long)DIM * SEQ,
                                           (long)SEQ * DIM);
    }
}

// round 13
// speedup vs baseline: 3.2993x; 1.1766x over previous
#include <cuda_runtime.h>
#include <cuda_fp16.h>
#include <cstdint>
#include <math.h>

// Problem constants
#define BATCH 16
#define SEQ   2048
#define DIM   512
#define NQKV  1536
#define MROWS (BATCH * SEQ)   // 32768
#define SCALE 0.125f

// GEMM tile config: CTA 256x128, BK=32, 512 threads (16 warps, 4x4), warp 64x32
#define BM 256
#define BN 128
#define BK 32
#define NTH 512

#define SROW 40                      // halves per row (32 + 8 pad)
#define O_AH 0
#define O_AL (BM * SROW * 2)         // 20480
#define O_BH (2 * BM * SROW * 2)     // 40960
#define O_BL (O_BH + BN * SROW * 2)  // 51200
#define STAGE_BYTES (O_BL + BN * SROW * 2)   // 61440
#define NSTAGES 3
#define SMEM_BYTES (NSTAGES * STAGE_BYTES)   // 184320

// ---------------------------------------------------------------------------
// Scratch (device globals — no allocation allowed)
// ---------------------------------------------------------------------------
__device__ __half g_xH[(size_t)MROWS * DIM];
__device__ __half g_xL[(size_t)MROWS * DIM];
__device__ __half g_wH[(size_t)NQKV * DIM];
__device__ __half g_wL[(size_t)NQKV * DIM];
__device__ float  g_bias[NQKV];
__device__ __half g_qkvH[(size_t)MROWS * NQKV];
__device__ __half g_qkvL[(size_t)MROWS * NQKV];
__device__ __half g_vtH[(size_t)MROWS * DIM];
__device__ __half g_vtL[(size_t)MROWS * DIM];
__device__ float  g_sim[(size_t)BATCH * SEQ * SEQ];
__device__ float2 g_stats[(size_t)MROWS];

// ---------------------------------------------------------------------------
// Helpers
// ---------------------------------------------------------------------------
__device__ __forceinline__ void split2(float a, float b, unsigned &h, unsigned &l) {
    __half2 hh = __floats2half2_rn(a, b);
    float2 r = __half22float2(hh);
    __half2 ll = __floats2half2_rn(a - r.x, b - r.y);
    h = *(unsigned*)&hh;
    l = *(unsigned*)&ll;
}

__device__ __forceinline__ void cpa16(unsigned dst, const void* src) {
    asm volatile("cp.async.cg.shared.global [%0], [%1], 16;"
                 :: "r"(dst), "l"(src) : "memory");
}
__device__ __forceinline__ void cpa_commit() {
    asm volatile("cp.async.commit_group;" ::: "memory");
}
__device__ __forceinline__ void cpa_wait1() {
    asm volatile("cp.async.wait_group 1;" ::: "memory");
}
__device__ __forceinline__ void cpa_wait0() {
    asm volatile("cp.async.wait_group 0;" ::: "memory");
}

#define MMA_F16(ACC, A0, A1, A2, A3, B0, B1)                                  \
    asm volatile(                                                             \
        "mma.sync.aligned.m16n8k16.row.col.f32.f16.f16.f32 "                 \
        "{%0,%1,%2,%3}, {%4,%5,%6,%7}, {%8,%9}, {%0,%1,%2,%3};"              \
        : "+f"(ACC[0]), "+f"(ACC[1]), "+f"(ACC[2]), "+f"(ACC[3])             \
        : "r"(A0), "r"(A1), "r"(A2), "r"(A3), "r"(B0), "r"(B1))

#define LDM_X4(R0, R1, R2, R3, ADDR)                                          \
    asm volatile("ldmatrix.sync.aligned.m8n8.x4.shared.b16 {%0,%1,%2,%3}, [%4];" \
        : "=r"(R0), "=r"(R1), "=r"(R2), "=r"(R3) : "r"(ADDR))

// ---------------------------------------------------------------------------
// Shared compute tile: 2 k-steps. X3=1 -> fp16x3 compensated; X3=0 -> hi only.
// ---------------------------------------------------------------------------
template <int X3>
__device__ __forceinline__ void compute_tile(unsigned stb, unsigned aoff,
                                             unsigned boff, float acc[4][4][4])
{
    #pragma unroll
    for (int ks = 0; ks < 2; ks++) {
        const unsigned kb = ks * 32;   // 16 halves = 32 bytes

        unsigned afH[4][4], afL[4][4];
        #pragma unroll
        for (int mt = 0; mt < 4; mt++) {
            const unsigned ah = stb + O_AH + aoff + mt * (16 * SROW * 2) + kb;
            LDM_X4(afH[mt][0], afH[mt][1], afH[mt][2], afH[mt][3], ah);
            if (X3) {
                const unsigned al = stb + O_AL + aoff + mt * (16 * SROW * 2) + kb;
                LDM_X4(afL[mt][0], afL[mt][1], afL[mt][2], afL[mt][3], al);
            }
        }
        unsigned bfH[4][2], bfL[4][2];
        #pragma unroll
        for (int p = 0; p < 2; p++) {
            const unsigned bh = stb + O_BH + boff + p * (16 * SROW * 2) + kb;
            LDM_X4(bfH[2*p][0], bfH[2*p][1], bfH[2*p+1][0], bfH[2*p+1][1], bh);
            if (X3) {
                const unsigned bl = stb + O_BL + boff + p * (16 * SROW * 2) + kb;
                LDM_X4(bfL[2*p][0], bfL[2*p][1], bfL[2*p+1][0], bfL[2*p+1][1], bl);
            }
        }
        #pragma unroll
        for (int mt = 0; mt < 4; mt++)
            #pragma unroll
            for (int nt = 0; nt < 4; nt++) {
                float* a4 = acc[mt][nt];
                if (X3) {
                    MMA_F16(a4, afL[mt][0], afL[mt][1], afL[mt][2], afL[mt][3],
                            bfH[nt][0], bfH[nt][1]);
                    MMA_F16(a4, afH[mt][0], afH[mt][1], afH[mt][2], afH[mt][3],
                            bfL[nt][0], bfL[nt][1]);
                }
                MMA_F16(a4, afH[mt][0], afH[mt][1], afH[mt][2], afH[mt][3],
                        bfH[nt][0], bfH[nt][1]);
            }
    }
}

// Per-thread ldmatrix offsets.
__device__ __forceinline__ void frag_offsets(int warp, int lane,
                                             unsigned &aoff, unsigned &boff)
{
    const int wm = warp >> 2, wn = warp & 3;
    const int t8 = lane >> 3, r8 = lane & 7;
    aoff = ((wm * 64 + ((t8 & 1) << 3) + r8) * SROW + ((t8 >> 1) << 3)) * 2;
    boff = ((wn * 32 + ((t8 >> 1) << 3) + r8) * SROW + ((t8 & 1) << 3)) * 2;
}

// ---------------------------------------------------------------------------
// NT GEMM with cp.async pipeline. X3: precision scheme.
// C[M,N] = alpha * A[M,K(ldA)] * (B[N,K(ldB)])^T + bias
// mode 0: write fp32 C (ldC).  mode 1: write split half oH/oL (ldC).
// ---------------------------------------------------------------------------
template <int X3>
__global__ __launch_bounds__(NTH, 1)
void gemm_f16(const __half* __restrict__ aHg, const __half* __restrict__ aLg,
              const __half* __restrict__ bHg, const __half* __restrict__ bLg,
              const float* __restrict__ bias, float* __restrict__ C,
              __half* __restrict__ oH, __half* __restrict__ oL,
              int M, int N, int K, int ldA, int ldB, int ldC,
              float alpha, int mode,
              long sA, long sB, long sC)
{
    extern __shared__ __align__(16) char dyn[];

    const long zb = blockIdx.z;
    aHg += zb * sA; if (X3) aLg += zb * sA;
    bHg += zb * sB; if (X3) bLg += zb * sB;
    if (C)  C  += zb * sC;
    if (oH) { oH += zb * sC; oL += zb * sC; }

    const int tid  = threadIdx.x;
    const int row0 = blockIdx.y * BM;
    const int col0 = blockIdx.x * BN;

    const int warp = tid >> 5;
    const int lane = tid & 31;
    const int wm   = warp >> 2;
    const int wn   = warp & 3;
    const int g    = lane >> 2;
    const int t4   = lane & 3;

    const unsigned sb = (unsigned)__cvta_generic_to_shared(dyn);
    unsigned aoff, boff;
    frag_offsets(warp, lane, aoff, boff);

    const int arow0 = tid >> 2;
    const int apart = (tid & 3) * 8;
    const __half* srcAH0 = aHg + (long)(row0 + arow0) * ldA + apart;
    const __half* srcAH1 = aHg + (long)(row0 + 128 + arow0) * ldA + apart;
    const __half* srcAL0 = X3 ? (aLg + (long)(row0 + arow0) * ldA + apart) : srcAH0;
    const __half* srcAL1 = X3 ? (aLg + (long)(row0 + 128 + arow0) * ldA + apart) : srcAH1;
    const __half* srcBH  = bHg + (long)(col0 + arow0) * ldB + apart;
    const __half* srcBL  = X3 ? (bLg + (long)(col0 + arow0) * ldB + apart) : srcBH;
    const unsigned dA0 = arow0 * (SROW * 2) + apart * 2;
    const unsigned dA1 = (128 + arow0) * (SROW * 2) + apart * 2;
    const unsigned dB  = arow0 * (SROW * 2) + apart * 2;

    const int NIT = K / BK;

#define ISSUE(STG, IT)                                                        \
    {                                                                         \
        const long ko = (long)(IT) * BK;                                      \
        const unsigned st = sb + (STG) * STAGE_BYTES;                         \
        cpa16(st + O_AH + dA0, srcAH0 + ko);                                  \
        cpa16(st + O_AH + dA1, srcAH1 + ko);                                  \
        cpa16(st + O_BH + dB,  srcBH  + ko);                                  \
        if (X3) {                                                             \
            cpa16(st + O_AL + dA0, srcAL0 + ko);                              \
            cpa16(st + O_AL + dA1, srcAL1 + ko);                              \
            cpa16(st + O_BL + dB,  srcBL  + ko);                              \
        }                                                                     \
        cpa_commit();                                                         \
    }

    float acc[4][4][4] = {};

    ISSUE(0, 0);
    ISSUE(1, 1);

    int cur = 0;
    for (int it = 0; it < NIT; it++) {
        if (it + 1 < NIT) cpa_wait1(); else cpa_wait0();
        __syncthreads();

        compute_tile<X3>(sb + cur * STAGE_BYTES, aoff, boff, acc);

        if (it + 2 < NIT) ISSUE((cur + 2) % NSTAGES, it + 2);
        if (++cur == NSTAGES) cur = 0;
    }
#undef ISSUE

    // ---- epilogue ----
    #pragma unroll
    for (int mt = 0; mt < 4; mt++) {
        const int r = row0 + wm * 64 + mt * 16 + g;
        #pragma unroll
        for (int nt = 0; nt < 4; nt++) {
            const int c = col0 + wn * 32 + nt * 8 + 2 * t4;
            float b0 = 0.f, b1 = 0.f;
            if (bias) { b0 = bias[c]; b1 = bias[c + 1]; }
            float2 v0, v1;
            v0.x = alpha * acc[mt][nt][0] + b0;
            v0.y = alpha * acc[mt][nt][1] + b1;
            v1.x = alpha * acc[mt][nt][2] + b0;
            v1.y = alpha * acc[mt][nt][3] + b1;
            if (mode == 0) {
                *(float2*)(C + (long)r * ldC + c)       = v0;
                *(float2*)(C + (long)(r + 8) * ldC + c) = v1;
            } else {
                unsigned h, l;
                split2(v0.x, v0.y, h, l);
                *(unsigned*)(oH + (long)r * ldC + c) = h;
                *(unsigned*)(oL + (long)r * ldC + c) = l;
                split2(v1.x, v1.y, h, l);
                *(unsigned*)(oH + (long)(r + 8) * ldC + c) = h;
                *(unsigned*)(oL + (long)(r + 8) * ldC + c) = l;
            }
        }
    }
}

// ---------------------------------------------------------------------------
// Fused attn@V GEMM: A = softmax(sim) on the fly; B = Vt split, cp.async.
// ---------------------------------------------------------------------------
__global__ __launch_bounds__(NTH, 1)
void gemm_av(const float* __restrict__ sim, const float2* __restrict__ stats,
             const __half* __restrict__ bHg, const __half* __restrict__ bLg,
             float* __restrict__ C, int N, int K,
             long sA, long sB, long sC)
{
    extern __shared__ __align__(16) char dyn[];

    const long zb = blockIdx.z;
    sim += zb * sA;
    bHg += zb * sB; bLg += zb * sB;
    C   += zb * sC;

    const int tid  = threadIdx.x;
    const int row0 = blockIdx.y * BM;
    const int col0 = blockIdx.x * BN;

    const int warp = tid >> 5;
    const int lane = tid & 31;
    const int wm   = warp >> 2;
    const int wn   = warp & 3;
    const int g    = lane >> 2;
    const int t4   = lane & 3;

    const unsigned sb = (unsigned)__cvta_generic_to_shared(dyn);
    unsigned aoff, boff;
    frag_offsets(warp, lane, aoff, boff);

    const int arow = tid >> 1;
    const int ak0  = (tid & 1) * 16;
    const float* srcA = sim + (long)(row0 + arow) * K + ak0;
    const float2 st = stats[zb * SEQ + row0 + arow];
    const float mx = st.x, inv = st.y;
    const unsigned dA = arow * (SROW * 2) + ak0 * 2;

    const int brow = tid >> 2;
    const int bpart = (tid & 3) * 8;
    const __half* srcBH = bHg + (long)(col0 + brow) * K + bpart;
    const __half* srcBL = bLg + (long)(col0 + brow) * K + bpart;
    const unsigned dB = brow * (SROW * 2) + bpart * 2;

    const int NIT = K / BK;
    float4 aReg[4];

#define LOADA(IT)                                                             \
    {                                                                         \
        const long ko = (long)(IT) * BK;                                      \
        _Pragma("unroll")                                                     \
        for (int i = 0; i < 4; i++)                                           \
            aReg[i] = *(const float4*)(srcA + ko + 4 * i);                    \
    }
#define STSA(STG)                                                             \
    {                                                                         \
        char* st_ = dyn + (STG) * STAGE_BYTES;                                \
        _Pragma("unroll")                                                     \
        for (int i = 0; i < 4; i++) {                                         \
            float p0 = __expf(aReg[i].x - mx) * inv;                          \
            float p1 = __expf(aReg[i].y - mx) * inv;                          \
            float p2 = __expf(aReg[i].z - mx) * inv;                          \
            float p3 = __expf(aReg[i].w - mx) * inv;                          \
            uint2 hh, ll;                                                     \
            split2(p0, p1, hh.x, ll.x);                                       \
            split2(p2, p3, hh.y, ll.y);                                       \
            *(uint2*)(st_ + O_AH + dA + 8 * i) = hh;                          \
            *(uint2*)(st_ + O_AL + dA + 8 * i) = ll;                          \
        }                                                                     \
    }
#define ISSUEB(STG, IT)                                                       \
    {                                                                         \
        const long ko = (long)(IT) * BK;                                      \
        const unsigned st = sb + (STG) * STAGE_BYTES;                         \
        cpa16(st + O_BH + dB, srcBH + ko);                                    \
        cpa16(st + O_BL + dB, srcBL + ko);                                    \
        cpa_commit();                                                         \
    }

    float acc[4][4][4] = {};

    LOADA(0); STSA(0);
    LOADA(1); STSA(1);
    ISSUEB(0, 0);
    ISSUEB(1, 1);

    int cur = 0;
    for (int it = 0; it < NIT; it++) {
        if (it + 1 < NIT) cpa_wait1(); else cpa_wait0();
        __syncthreads();

        if (it + 2 < NIT) LOADA(it + 2);

        compute_tile<1>(sb + cur * STAGE_BYTES, aoff, boff, acc);

        if (it + 2 < NIT) {
            STSA((cur + 2) % NSTAGES);
            ISSUEB((cur + 2) % NSTAGES, it + 2);
        }
        if (++cur == NSTAGES) cur = 0;
    }
#undef LOADA
#undef STSA
#undef ISSUEB

    #pragma unroll
    for (int mt = 0; mt < 4; mt++) {
        const int r = row0 + wm * 64 + mt * 16 + g;
        #pragma unroll
        for (int nt = 0; nt < 4; nt++) {
            const int c = col0 + wn * 32 + nt * 8 + 2 * t4;
            float2 v0, v1;
            v0.x = acc[mt][nt][0];
            v0.y = acc[mt][nt][1];
            v1.x = acc[mt][nt][2];
            v1.y = acc[mt][nt][3];
            *(float2*)(C + (long)r * N + c)       = v0;
            *(float2*)(C + (long)(r + 8) * N + c) = v1;
        }
    }
}

// ---------------------------------------------------------------------------
// Row stats: max + 1/sum(exp) over SEQ cols. One block per row.
// ---------------------------------------------------------------------------
__global__ __launch_bounds__(256)
void rowstat(const float* __restrict__ sim, float2* __restrict__ stats)
{
    const float* p = sim + (long)blockIdx.x * SEQ;
    const int tid = threadIdx.x;

    float v[8];
    float mx = -1e30f;
    #pragma unroll
    for (int i = 0; i < 8; i++) {
        v[i] = p[tid + i * 256];
        mx = fmaxf(mx, v[i]);
    }
    #pragma unroll
    for (int o = 16; o; o >>= 1)
        mx = fmaxf(mx, __shfl_xor_sync(0xffffffffu, mx, o));
    __shared__ float red[8];
    if ((tid & 31) == 0) red[tid >> 5] = mx;
    __syncthreads();
    mx = red[0];
    #pragma unroll
    for (int w = 1; w < 8; w++) mx = fmaxf(mx, red[w]);

    float s = 0.f;
    #pragma unroll
    for (int i = 0; i < 8; i++)
        s += __expf(v[i] - mx);
    #pragma unroll
    for (int o = 16; o; o >>= 1)
        s += __shfl_xor_sync(0xffffffffu, s, o);
    __syncthreads();
    if ((tid & 31) == 0) red[tid >> 5] = s;
    __syncthreads();
    s = red[0];
    #pragma unroll
    for (int w = 1; w < 8; w++) s += red[w];

    if (tid == 0) {
        float2 st;
        st.x = mx;
        st.y = 1.0f / s;
        stats[blockIdx.x] = st;
    }
}

// ---------------------------------------------------------------------------
// Elementwise split: fp32 -> half hi/lo
// ---------------------------------------------------------------------------
__global__ __launch_bounds__(256)
void split_hl(const float* __restrict__ in, __half* __restrict__ oH,
              __half* __restrict__ oL, long n4)
{
    const long i = (long)blockIdx.x * 256 + threadIdx.x;
    if (i >= n4) return;
    float4 v = *(const float4*)(in + 4 * i);
    uint2 hh, ll;
    split2(v.x, v.y, hh.x, ll.x);
    split2(v.z, v.w, hh.y, ll.y);
    *(uint2*)(oH + 4 * i) = hh;
    *(uint2*)(oL + 4 * i) = ll;
}

// ---------------------------------------------------------------------------
// Transpose + split: in[R,C] fp32 -> oH/oL[C,R] half (square 512x512 weights).
// ---------------------------------------------------------------------------
__global__ __launch_bounds__(256)
void transpose_split(const float* __restrict__ in,
                     __half* __restrict__ oH, __half* __restrict__ oL,
                     int R, int C)
{
    __shared__ float t[32][33];
    const int tx = threadIdx.x & 31;
    const int ty = threadIdx.x >> 5;
    const int bx = blockIdx.x * 32;
    const int by = blockIdx.y * 32;
    #pragma unroll
    for (int jj = 0; jj < 4; jj++)
        t[ty + 8 * jj][tx] = in[(long)(by + ty + 8 * jj) * C + bx + tx];
    __syncthreads();
    #pragma unroll
    for (int jj = 0; jj < 4; jj++) {
        const float f = t[tx][ty + 8 * jj];
        const __half h = __float2half_rn(f);
        const __half l = __float2half_rn(f - __half2float(h));
        const long o = (long)(bx + ty + 8 * jj) * R + by + tx;
        oH[o] = h;
        oL[o] = l;
    }
}

// ---------------------------------------------------------------------------
// V transpose from strided qkv split layout: vt[b][d][s] = v[b][s][d]
// ---------------------------------------------------------------------------
__global__ __launch_bounds__(256)
void transpose_v(const __half* __restrict__ qkvH, const __half* __restrict__ qkvL,
                 __half* __restrict__ vtH, __half* __restrict__ vtL)
{
    __shared__ float t[32][33];
    const long inB  = (long)blockIdx.z * SEQ * NQKV;
    const long outB = (long)blockIdx.z * SEQ * DIM;
    const int tx = threadIdx.x & 31;
    const int ty = threadIdx.x >> 5;
    const int bx = blockIdx.x * 32;   // d base
    const int by = blockIdx.y * 32;   // s base
    #pragma unroll
    for (int jj = 0; jj < 4; jj++) {
        const long idx = inB + (long)(by + ty + 8 * jj) * NQKV + 1024 + bx + tx;
        t[ty + 8 * jj][tx] = __half2float(qkvH[idx]) + __half2float(qkvL[idx]);
    }
    __syncthreads();
    #pragma unroll
    for (int jj = 0; jj < 4; jj++) {
        const float f = t[tx][ty + 8 * jj];
        const __half h = __float2half_rn(f);
        const __half l = __float2half_rn(f - __half2float(h));
        const long o = outB + (long)(bx + ty + 8 * jj) * SEQ + by + tx;
        vtH[o] = h;
        vtL[o] = l;
    }
}

// ---------------------------------------------------------------------------
// Bias concat: [bq | bk | bv] -> g_bias[1536]
// ---------------------------------------------------------------------------
__global__ __launch_bounds__(256)
void concat_bias(const float* __restrict__ bq, const float* __restrict__ bk,
                 const float* __restrict__ bv, float* __restrict__ b)
{
    const int i = blockIdx.x * 256 + threadIdx.x;
    if (i < 512)       b[i] = bq[i];
    else if (i < 1024) b[i] = bk[i - 512];
    else if (i < 1536) b[i] = bv[i - 1024];
}

// ---------------------------------------------------------------------------
// Launch
// ---------------------------------------------------------------------------
extern "C" void kernel_launch(void* const* d_in, const int* in_sizes, int n_in,
                              void* d_out, int out_size)
{
    const float* x  = (const float*)d_in[0];
    const float* Wq = (const float*)d_in[1];
    const float* bq = (const float*)d_in[2];
    const float* Wk = (const float*)d_in[3];
    const float* bk = (const float*)d_in[4];
    const float* Wv = (const float*)d_in[5];
    const float* bv = (const float*)d_in[6];
    float* out = (float*)d_out;

    __half *xH, *xL, *wH, *wL, *qkvH, *qkvL, *vtH, *vtL;
    float *sim, *bias;
    float2* stats;
    cudaGetSymbolAddress((void**)&xH, g_xH);
    cudaGetSymbolAddress((void**)&xL, g_xL);
    cudaGetSymbolAddress((void**)&wH, g_wH);
    cudaGetSymbolAddress((void**)&wL, g_wL);
    cudaGetSymbolAddress((void**)&bias, g_bias);
    cudaGetSymbolAddress((void**)&qkvH, g_qkvH);
    cudaGetSymbolAddress((void**)&qkvL, g_qkvL);
    cudaGetSymbolAddress((void**)&vtH, g_vtH);
    cudaGetSymbolAddress((void**)&vtL, g_vtL);
    cudaGetSymbolAddress((void**)&sim, g_sim);
    cudaGetSymbolAddress((void**)&stats, g_stats);

    cudaFuncSetAttribute(gemm_f16<1>,
                         cudaFuncAttributeMaxDynamicSharedMemorySize, SMEM_BYTES);
    cudaFuncSetAttribute(gemm_f16<0>,
                         cudaFuncAttributeMaxDynamicSharedMemorySize, SMEM_BYTES);
    cudaFuncSetAttribute(gemm_av,
                         cudaFuncAttributeMaxDynamicSharedMemorySize, SMEM_BYTES);

    // 0a) split x into half hi/lo
    {
        const long n4 = (long)MROWS * DIM / 4;
        split_hl<<<(unsigned)((n4 + 255) / 256), 256>>>(x, xH, xL, n4);
    }
    // 0b) transpose+split each weight into its [512,512] slab of [1536,512]
    {
        dim3 grid(DIM / 32, DIM / 32, 1);
        transpose_split<<<grid, 256>>>(Wq, wH, wL, DIM, DIM);
        transpose_split<<<grid, 256>>>(Wk, wH + (size_t)DIM * DIM,
                                       wL + (size_t)DIM * DIM, DIM, DIM);
        transpose_split<<<grid, 256>>>(Wv, wH + 2 * (size_t)DIM * DIM,
                                       wL + 2 * (size_t)DIM * DIM, DIM, DIM);
    }
    // 0c) bias concat
    concat_bias<<<6, 256>>>(bq, bk, bv, bias);

    // 1) Fused QKV projection: [32768,1536] = x @ [Wq|Wk|Wv]^T + bias, split out
    {
        dim3 grid(NQKV / BN, MROWS / BM, 1);
        gemm_f16<1><<<grid, NTH, SMEM_BYTES>>>(xH, xL, wH, wL, bias,
                                               nullptr, qkvH, qkvL,
                                               MROWS, NQKV, DIM,
                                               DIM, DIM, NQKV,
                                               1.0f, 1, 0, 0, 0);
    }

    // 1b) transpose V slab -> vtH/vtL [b][d][s]
    {
        dim3 grid(DIM / 32, SEQ / 32, BATCH);
        transpose_v<<<grid, 256>>>(qkvH, qkvL, vtH, vtL);
    }

    // 2) sim[b] = Q[b] @ K[b]^T * SCALE (fp16 x1, hi parts only) -> fp32
    {
        dim3 grid(SEQ / BN, SEQ / BM, BATCH);
        gemm_f16<0><<<grid, NTH, SMEM_BYTES>>>(qkvH, nullptr,
                                               qkvH + 512, nullptr, nullptr,
                                               sim, nullptr, nullptr,
                                               SEQ, SEQ, DIM,
                                               NQKV, NQKV, SEQ,
                                               SCALE, 0,
                                               (long)SEQ * NQKV,
                                               (long)SEQ * NQKV,
                                               (long)SEQ * SEQ);
    }

    // 3) row stats (max, 1/sum)
    rowstat<<<MROWS, 256>>>(sim, stats);

    // 4) out[b] = softmax(sim[b]) @ Vt[b]^T -> fp32 (softmax fused in loader)
    {
        dim3 grid(DIM / BN, SEQ / BM, BATCH);
        gemm_av<<<grid, NTH, SMEM_BYTES>>>(sim, stats, vtH, vtL, out,
                                           DIM, SEQ,
                                           (long)SEQ * SEQ, (long)DIM * SEQ,
                                           (long)SEQ * DIM);
    }
}